// round 3
// baseline (speedup 1.0000x reference)
#include <cuda_runtime.h>
#include <math.h>

#define MIN_ROUGHNESS 0.08f
#define MAX_ROUGHNESS 0.5f
#define N_MIPS 6

// Spec mip texel counts (6 faces each): 512,256,128,64,32,16
// counts: 1572864, 393216, 98304, 24576, 6144, 1536  -> total 2096640
#define SPEC_TOTAL_TEXELS 2096640
#define DIFF_TEXELS 1536

__constant__ int SPEC_OFF[7] = {0, 1572864, 1966080, 2064384, 2088960, 2095104, 2096640};

__device__ float4 g_spec4[SPEC_TOTAL_TEXELS];
__device__ float4 g_diff4[DIFF_TEXELS];

struct SpecTable {
    const float* p[N_MIPS];
};

struct float3x { float x, y, z; };

// ---------------------------------------------------------------------------
// Preprocess: RGB (packed) -> RGBA (float4) for all spec mips + diffuse cube.
// 4 texels per thread: 3 x LDG.128 in, 4 x STG.128 out.
// ---------------------------------------------------------------------------
__global__ void __launch_bounds__(256)
convert_rgba_kernel(SpecTable specs, const float* __restrict__ diffuse) {
    const int quads_spec = SPEC_TOTAL_TEXELS / 4;          // 524160
    const int quads_total = quads_spec + DIFF_TEXELS / 4;  // +384
    int q = blockIdx.x * blockDim.x + threadIdx.x;
    if (q >= quads_total) return;

    const float* in;
    float4* o;
    if (q < quads_spec) {
        int t = q * 4;
        int lvl = 0;
        if (t >= 1572864) lvl = 1;
        if (t >= 1966080) lvl = 2;
        if (t >= 2064384) lvl = 3;
        if (t >= 2088960) lvl = 4;
        if (t >= 2095104) lvl = 5;
        int loff = SPEC_OFF[lvl];
        in = specs.p[lvl] + (size_t)(t - loff) * 3;
        o = g_spec4 + t;
    } else {
        int t = (q - quads_spec) * 4;
        in = diffuse + (size_t)t * 3;
        o = g_diff4 + t;
    }

    float4 a = __ldg((const float4*)in + 0);
    float4 b = __ldg((const float4*)in + 1);
    float4 c = __ldg((const float4*)in + 2);
    o[0] = make_float4(a.x, a.y, a.z, 0.0f);
    o[1] = make_float4(a.w, b.x, b.y, 0.0f);
    o[2] = make_float4(b.z, b.w, c.x, 0.0f);
    o[3] = make_float4(c.y, c.z, c.w, 0.0f);
}

// ---------------------------------------------------------------------------
// Main shading kernel
// ---------------------------------------------------------------------------
__device__ __forceinline__ float3x cube_bilinear4(const float4* __restrict__ tex,
                                                  int R, int face, float u, float v) {
    float Rf = (float)R;
    float tu = fmaf(u, 0.5f * Rf, 0.5f * Rf - 0.5f);
    float tv = fmaf(v, 0.5f * Rf, 0.5f * Rf - 0.5f);
    float x0f = floorf(tu);
    float y0f = floorf(tv);
    float fx = tu - x0f;
    float fy = tv - y0f;
    int x0 = (int)fminf(fmaxf(x0f, 0.0f), Rf - 1.0f);
    int x1 = (int)fminf(fmaxf(x0f + 1.0f, 0.0f), Rf - 1.0f);
    int y0 = (int)fminf(fmaxf(y0f, 0.0f), Rf - 1.0f);
    int y1 = (int)fminf(fmaxf(y0f + 1.0f, 0.0f), Rf - 1.0f);

    int baseF = face * R * R;
    float4 c00 = __ldg(tex + baseF + y0 * R + x0);
    float4 c01 = __ldg(tex + baseF + y0 * R + x1);
    float4 c10 = __ldg(tex + baseF + y1 * R + x0);
    float4 c11 = __ldg(tex + baseF + y1 * R + x1);

    float w00 = (1.0f - fx) * (1.0f - fy);
    float w01 = fx * (1.0f - fy);
    float w10 = (1.0f - fx) * fy;
    float w11 = fx * fy;

    float3x r;
    r.x = c00.x * w00 + c01.x * w01 + c10.x * w10 + c11.x * w11;
    r.y = c00.y * w00 + c01.y * w01 + c10.y * w10 + c11.y * w11;
    r.z = c00.z * w00 + c01.z * w01 + c10.z * w10 + c11.z * w11;
    return r;
}

__device__ __forceinline__ void cube_face_uv(float x, float y, float z,
                                             int& face, float& u, float& v) {
    float ax = fabsf(x), ay = fabsf(y), az = fabsf(z);
    bool is_x = (ax >= ay) && (ax >= az);
    bool is_y = (!is_x) && (ay >= az);
    face = is_x ? (x >= 0.0f ? 0 : 1)
                : (is_y ? (y >= 0.0f ? 2 : 3)
                        : (z >= 0.0f ? 4 : 5));
    float ma = fmaxf(is_x ? ax : (is_y ? ay : az), 1e-20f);
    float un = (face == 0) ? -z : (face == 1) ? z : (face == 5) ? -x : x;
    float vn = (face == 2) ? z : (face == 3) ? -z : -y;
    float inv = 1.0f / ma;
    u = un * inv;
    v = vn * inv;
}

__device__ __forceinline__ float linear2srgb(float x) {
    if (x > 0.0031308f) {
        return 1.055f * __powf(x, 1.0f / 2.4f) - 0.055f;
    }
    return 12.92f * x;
}

__device__ __forceinline__ void shade_pixel(
    float px, float py, float pz,
    float nx, float ny, float nz,
    float bcx, float bcy, float bcz,
    float met, float rough,
    float vx, float vy, float vz,
    const float* __restrict__ fg_lut,
    float& ox, float& oy, float& oz)
{
    // wo = normalize(view - pos)
    float wx = vx - px, wy = vy - py, wz = vz - pz;
    float wlen2 = fmaxf(wx * wx + wy * wy + wz * wz, 1e-20f);
    float winv = rsqrtf(wlen2);
    wx *= winv; wy *= winv; wz *= winv;

    float om = 1.0f - met;
    float dax = om * bcx, day = om * bcy, daz = om * bcz;
    float sax = 0.04f * om + met * bcx;
    float say = 0.04f * om + met * bcy;
    float saz = 0.04f * om + met * bcz;

    float d = wx * nx + wy * ny + wz * nz;
    float rx = 2.0f * d * nx - wx;
    float ry = 2.0f * d * ny - wy;
    float rz = 2.0f * d * nz - wz;
    float rlen2 = fmaxf(rx * rx + ry * ry + rz * rz, 1e-20f);
    float rinv = rsqrtf(rlen2);
    rx *= rinv; ry *= rinv; rz *= rinv;

    // ambient from diffuse cubemap (16^2)
    int dface; float du, dv;
    cube_face_uv(nx, ny, nz, dface, du, dv);
    float3x ambient = cube_bilinear4(g_diff4, 16, dface, du, dv);

    float dlx = ambient.x * dax;
    float dly = ambient.y * day;
    float dlz = ambient.z * daz;

    // FG LUT (256x256x2, clamp)
    float NdotV = fmaxf(d, 0.0001f);
    float fg0, fg1;
    {
        float tu = NdotV * 256.0f - 0.5f;
        float tv = rough * 256.0f - 0.5f;
        float x0f = floorf(tu);
        float y0f = floorf(tv);
        float fx = tu - x0f;
        float fy = tv - y0f;
        int x0 = (int)fminf(fmaxf(x0f, 0.0f), 255.0f);
        int x1 = (int)fminf(fmaxf(x0f + 1.0f, 0.0f), 255.0f);
        int y0 = (int)fminf(fmaxf(y0f, 0.0f), 255.0f);
        int y1 = (int)fminf(fmaxf(y0f + 1.0f, 0.0f), 255.0f);
        int i00 = (y0 * 256 + x0) * 2;
        int i01 = (y0 * 256 + x1) * 2;
        int i10 = (y1 * 256 + x0) * 2;
        int i11 = (y1 * 256 + x1) * 2;
        float w00 = (1.0f - fx) * (1.0f - fy);
        float w01 = fx * (1.0f - fy);
        float w10 = (1.0f - fx) * fy;
        float w11 = fx * fy;
        float2 c00 = __ldg((const float2*)(fg_lut + i00));
        float2 c01 = __ldg((const float2*)(fg_lut + i01));
        float2 c10 = __ldg((const float2*)(fg_lut + i10));
        float2 c11 = __ldg((const float2*)(fg_lut + i11));
        fg0 = c00.x * w00 + c01.x * w01 + c10.x * w10 + c11.x * w11;
        fg1 = c00.y * w00 + c01.y * w01 + c10.y * w10 + c11.y * w11;
    }

    // mip
    float mip;
    {
        const float L = (float)N_MIPS;
        float lo = (fminf(fmaxf(rough, MIN_ROUGHNESS), MAX_ROUGHNESS) - MIN_ROUGHNESS)
                   * ((L - 2.0f) / (MAX_ROUGHNESS - MIN_ROUGHNESS));
        float hi = (fminf(fmaxf(rough, MAX_ROUGHNESS), 1.0f) - MAX_ROUGHNESS)
                   * (1.0f / (1.0f - MAX_ROUGHNESS)) + (L - 2.0f);
        mip = (rough < MAX_ROUGHNESS) ? lo : hi;
        mip = fminf(fmaxf(mip, 0.0f), L - 1.0f);
    }

    int sface; float su, sv;
    cube_face_uv(rx, ry, rz, sface, su, sv);

    int l0 = (int)floorf(mip);
    if (l0 > N_MIPS - 1) l0 = N_MIPS - 1;
    float f = mip - (float)l0;
    int l1 = l0 + 1;
    if (l1 > N_MIPS - 1) l1 = N_MIPS - 1;

    const float4* t0 = g_spec4 + SPEC_OFF[l0];
    const float4* t1 = g_spec4 + SPEC_OFF[l1];
    int R0 = 512 >> l0;
    int R1 = 512 >> l1;

    float3x s0 = cube_bilinear4(t0, R0, sface, su, sv);
    float3x s1 = cube_bilinear4(t1, R1, sface, su, sv);

    float spx = (1.0f - f) * s0.x + f * s1.x;
    float spy = (1.0f - f) * s0.y + f * s1.y;
    float spz = (1.0f - f) * s0.z + f * s1.z;

    float refx = sax * fg0 + fg1;
    float refy = say * fg0 + fg1;
    float refz = saz * fg0 + fg1;

    float cx = fminf(fmaxf(spx * refx + dlx, 0.0f), 1.0f);
    float cy = fminf(fmaxf(spy * refy + dly, 0.0f), 1.0f);
    float cz = fminf(fmaxf(spz * refz + dlz, 0.0f), 1.0f);

    ox = linear2srgb(cx);
    oy = linear2srgb(cy);
    oz = linear2srgb(cz);
}

__global__ void __launch_bounds__(256)
envlight_kernel4(const float* __restrict__ gb_pos,
                 const float* __restrict__ gb_normal,
                 const float* __restrict__ basecolor,
                 const float* __restrict__ metallic,
                 const float* __restrict__ roughness,
                 const float* __restrict__ view_pos,
                 const float* __restrict__ fg_lut,
                 float* __restrict__ out,
                 int n) {
    int q = blockIdx.x * blockDim.x + threadIdx.x;
    int base = q * 4;
    if (base >= n) return;

    float vx = __ldg(view_pos + 0);
    float vy = __ldg(view_pos + 1);
    float vz = __ldg(view_pos + 2);

    float P[12], N[12], BC[12], MET[4], RGH[4];
    bool full = (base + 4 <= n);

    if (full) {
        const float4* p4 = (const float4*)gb_pos + q * 3;
        const float4* n4 = (const float4*)gb_normal + q * 3;
        const float4* b4 = (const float4*)basecolor + q * 3;
        #pragma unroll
        for (int k = 0; k < 3; k++) {
            float4 a = __ldg(p4 + k);
            P[k * 4 + 0] = a.x; P[k * 4 + 1] = a.y; P[k * 4 + 2] = a.z; P[k * 4 + 3] = a.w;
            float4 b = __ldg(n4 + k);
            N[k * 4 + 0] = b.x; N[k * 4 + 1] = b.y; N[k * 4 + 2] = b.z; N[k * 4 + 3] = b.w;
            float4 c = __ldg(b4 + k);
            BC[k * 4 + 0] = c.x; BC[k * 4 + 1] = c.y; BC[k * 4 + 2] = c.z; BC[k * 4 + 3] = c.w;
        }
        float4 m = __ldg((const float4*)metallic + q);
        MET[0] = m.x; MET[1] = m.y; MET[2] = m.z; MET[3] = m.w;
        float4 r = __ldg((const float4*)roughness + q);
        RGH[0] = r.x; RGH[1] = r.y; RGH[2] = r.z; RGH[3] = r.w;
    } else {
        #pragma unroll
        for (int k = 0; k < 4; k++) {
            int i = base + k;
            int ii = (i < n) ? i : (n - 1);
            P[3 * k + 0] = gb_pos[ii * 3 + 0];
            P[3 * k + 1] = gb_pos[ii * 3 + 1];
            P[3 * k + 2] = gb_pos[ii * 3 + 2];
            N[3 * k + 0] = gb_normal[ii * 3 + 0];
            N[3 * k + 1] = gb_normal[ii * 3 + 1];
            N[3 * k + 2] = gb_normal[ii * 3 + 2];
            BC[3 * k + 0] = basecolor[ii * 3 + 0];
            BC[3 * k + 1] = basecolor[ii * 3 + 1];
            BC[3 * k + 2] = basecolor[ii * 3 + 2];
            MET[k] = metallic[ii];
            RGH[k] = roughness[ii];
        }
    }

    float O[12];
    #pragma unroll
    for (int k = 0; k < 4; k++) {
        float ox, oy, oz;
        shade_pixel(P[3 * k + 0], P[3 * k + 1], P[3 * k + 2],
                    N[3 * k + 0], N[3 * k + 1], N[3 * k + 2],
                    BC[3 * k + 0], BC[3 * k + 1], BC[3 * k + 2],
                    MET[k], RGH[k], vx, vy, vz,
                    fg_lut, ox, oy, oz);
        O[3 * k + 0] = ox; O[3 * k + 1] = oy; O[3 * k + 2] = oz;
    }

    if (full) {
        float4* o4 = (float4*)out + q * 3;
        #pragma unroll
        for (int k = 0; k < 3; k++) {
            float4 w;
            w.x = O[k * 4 + 0]; w.y = O[k * 4 + 1]; w.z = O[k * 4 + 2]; w.w = O[k * 4 + 3];
            o4[k] = w;
        }
    } else {
        #pragma unroll
        for (int k = 0; k < 4; k++) {
            int i = base + k;
            if (i < n) {
                out[i * 3 + 0] = O[3 * k + 0];
                out[i * 3 + 1] = O[3 * k + 1];
                out[i * 3 + 2] = O[3 * k + 2];
            }
        }
    }
}

extern "C" void kernel_launch(void* const* d_in, const int* in_sizes, int n_in,
                              void* d_out, int out_size) {
    const float* gb_pos    = (const float*)d_in[0];
    const float* gb_normal = (const float*)d_in[1];
    const float* basecolor = (const float*)d_in[2];
    const float* metallic  = (const float*)d_in[3];
    const float* roughness = (const float*)d_in[4];
    const float* view_pos  = (const float*)d_in[5];
    const float* diffuse   = (const float*)d_in[6];
    const float* fg_lut    = (const float*)d_in[7];

    SpecTable specs;
    specs.p[0] = (const float*)d_in[8];
    specs.p[1] = (const float*)d_in[9];
    specs.p[2] = (const float*)d_in[10];
    specs.p[3] = (const float*)d_in[11];
    specs.p[4] = (const float*)d_in[12];
    specs.p[5] = (const float*)d_in[13];

    float* out = (float*)d_out;
    int n = in_sizes[0] / 3;

    // Pass 1: repack RGB -> RGBA into device-global scratch
    {
        int quads_total = SPEC_TOTAL_TEXELS / 4 + DIFF_TEXELS / 4;
        int threads = 256;
        int blocks = (quads_total + threads - 1) / threads;
        convert_rgba_kernel<<<blocks, threads>>>(specs, diffuse);
    }

    // Pass 2: shade
    {
        int threads = 256;
        int quads = (n + 3) / 4;
        int blocks = (quads + threads - 1) / threads;
        envlight_kernel4<<<blocks, threads>>>(gb_pos, gb_normal, basecolor, metallic,
                                              roughness, view_pos, fg_lut, out, n);
    }
}

// round 4
// speedup vs baseline: 1.0672x; 1.0672x over previous
#include <cuda_runtime.h>
#include <math.h>

#define MIN_ROUGHNESS 0.08f
#define MAX_ROUGHNESS 0.5f
#define N_MIPS 6

struct SpecTable {
    const float* p[N_MIPS];
};

struct float3x { float x, y, z; };

__device__ __forceinline__ float3x cube_sample_bilinear(const float* __restrict__ tex,
                                                        int R, int face, float u, float v) {
    float Rf = (float)R;
    float tu = fmaf(u, 0.5f * Rf, 0.5f * Rf - 0.5f);
    float tv = fmaf(v, 0.5f * Rf, 0.5f * Rf - 0.5f);
    float x0f = floorf(tu);
    float y0f = floorf(tv);
    float fx = tu - x0f;
    float fy = tv - y0f;
    int x0 = (int)fminf(fmaxf(x0f, 0.0f), Rf - 1.0f);
    int x1 = (int)fminf(fmaxf(x0f + 1.0f, 0.0f), Rf - 1.0f);
    int y0 = (int)fminf(fmaxf(y0f, 0.0f), Rf - 1.0f);
    int y1 = (int)fminf(fmaxf(y0f + 1.0f, 0.0f), Rf - 1.0f);

    int baseF = face * R * R;
    int i00 = (baseF + y0 * R + x0) * 3;
    int i01 = (baseF + y0 * R + x1) * 3;
    int i10 = (baseF + y1 * R + x0) * 3;
    int i11 = (baseF + y1 * R + x1) * 3;

    float w00 = (1.0f - fx) * (1.0f - fy);
    float w01 = fx * (1.0f - fy);
    float w10 = (1.0f - fx) * fy;
    float w11 = fx * fy;

    float3x r;
    r.x = __ldg(tex + i00 + 0) * w00 + __ldg(tex + i01 + 0) * w01 +
          __ldg(tex + i10 + 0) * w10 + __ldg(tex + i11 + 0) * w11;
    r.y = __ldg(tex + i00 + 1) * w00 + __ldg(tex + i01 + 1) * w01 +
          __ldg(tex + i10 + 1) * w10 + __ldg(tex + i11 + 1) * w11;
    r.z = __ldg(tex + i00 + 2) * w00 + __ldg(tex + i01 + 2) * w01 +
          __ldg(tex + i10 + 2) * w10 + __ldg(tex + i11 + 2) * w11;
    return r;
}

// Scale-invariant: vector need NOT be normalized.
__device__ __forceinline__ void cube_face_uv(float x, float y, float z,
                                             int& face, float& u, float& v) {
    float ax = fabsf(x), ay = fabsf(y), az = fabsf(z);
    bool is_x = (ax >= ay) && (ax >= az);
    bool is_y = (!is_x) && (ay >= az);
    face = is_x ? (x >= 0.0f ? 0 : 1)
                : (is_y ? (y >= 0.0f ? 2 : 3)
                        : (z >= 0.0f ? 4 : 5));
    float ma = fmaxf(is_x ? ax : (is_y ? ay : az), 1e-20f);
    float un = (face == 0) ? -z : (face == 1) ? z : (face == 5) ? -x : x;
    float vn = (face == 2) ? z : (face == 3) ? -z : -y;
    float inv = __fdividef(1.0f, ma);   // MUFU.RCP, no Newton
    u = un * inv;
    v = vn * inv;
}

// x^(1/2.4) via MUFU.LG2 + polynomial exp2 (no MUFU.EX2).
// y = log2(x)/2.4 in (-3.47, 0]; exp2(y) = 2^floor(y) * poly(frac).
// Degree-5 Taylor of 2^t on [0,1): max rel err < 1e-4 (budget 1e-3).
__device__ __forceinline__ float linear2srgb(float x) {
    float l = __log2f(x);
    float y = l * (1.0f / 2.4f);
    float fl = floorf(y);
    float t = y - fl;
    float p = fmaf(t,
              fmaf(t,
              fmaf(t,
              fmaf(t,
              fmaf(t, 0.0013333558f, 0.0096181291f),
                       0.0555041087f),
                       0.2402265070f),
                       0.6931471806f),
                       1.0f);
    int e = (int)fl;                       // fl in [-4, 0]
    float r = __int_as_float(__float_as_int(p) + (e << 23));
    float hi = fmaf(1.055f, r, -0.055f);
    return (x > 0.0031308f) ? hi : 12.92f * x;
}

__device__ __forceinline__ void shade_pixel(
    float px, float py, float pz,
    float nx, float ny, float nz,
    float bcx, float bcy, float bcz,
    float met, float rough,
    float vx, float vy, float vz,
    const float* __restrict__ diffuse_cube,
    const float* __restrict__ fg_lut,
    const SpecTable& specs,
    float& ox, float& oy, float& oz)
{
    // wo = normalize(view - pos)
    float wx = vx - px, wy = vy - py, wz = vz - pz;
    float wlen2 = fmaxf(wx * wx + wy * wy + wz * wz, 1e-20f);
    float winv = rsqrtf(wlen2);
    wx *= winv; wy *= winv; wz *= winv;

    float om = 1.0f - met;
    float dax = om * bcx, day = om * bcy, daz = om * bcz;
    float sax = 0.04f * om + met * bcx;
    float say = 0.04f * om + met * bcy;
    float saz = 0.04f * om + met * bcz;

    float d = wx * nx + wy * ny + wz * nz;
    // reflvec left UNNORMALIZED: cube_face_uv is scale-invariant, so
    // face/u/v are identical to the normalized version (exact).
    float rx = 2.0f * d * nx - wx;
    float ry = 2.0f * d * ny - wy;
    float rz = 2.0f * d * nz - wz;

    // ambient from diffuse cubemap (16^2)
    int dface; float du, dv;
    cube_face_uv(nx, ny, nz, dface, du, dv);
    float3x ambient = cube_sample_bilinear(diffuse_cube, 16, dface, du, dv);

    float dlx = ambient.x * dax;
    float dly = ambient.y * day;
    float dlz = ambient.z * daz;

    // FG LUT (256x256x2, clamp)
    float NdotV = fmaxf(d, 0.0001f);
    float fg0, fg1;
    {
        float tu = NdotV * 256.0f - 0.5f;
        float tv = rough * 256.0f - 0.5f;
        float x0f = floorf(tu);
        float y0f = floorf(tv);
        float fx = tu - x0f;
        float fy = tv - y0f;
        int x0 = (int)fminf(fmaxf(x0f, 0.0f), 255.0f);
        int x1 = (int)fminf(fmaxf(x0f + 1.0f, 0.0f), 255.0f);
        int y0 = (int)fminf(fmaxf(y0f, 0.0f), 255.0f);
        int y1 = (int)fminf(fmaxf(y0f + 1.0f, 0.0f), 255.0f);
        int i00 = (y0 * 256 + x0) * 2;
        int i01 = (y0 * 256 + x1) * 2;
        int i10 = (y1 * 256 + x0) * 2;
        int i11 = (y1 * 256 + x1) * 2;
        float w00 = (1.0f - fx) * (1.0f - fy);
        float w01 = fx * (1.0f - fy);
        float w10 = (1.0f - fx) * fy;
        float w11 = fx * fy;
        float2 c00 = __ldg((const float2*)(fg_lut + i00));
        float2 c01 = __ldg((const float2*)(fg_lut + i01));
        float2 c10 = __ldg((const float2*)(fg_lut + i10));
        float2 c11 = __ldg((const float2*)(fg_lut + i11));
        fg0 = c00.x * w00 + c01.x * w01 + c10.x * w10 + c11.x * w11;
        fg1 = c00.y * w00 + c01.y * w01 + c10.y * w10 + c11.y * w11;
    }

    // mip
    float mip;
    {
        const float L = (float)N_MIPS;
        float lo = (fminf(fmaxf(rough, MIN_ROUGHNESS), MAX_ROUGHNESS) - MIN_ROUGHNESS)
                   * ((L - 2.0f) / (MAX_ROUGHNESS - MIN_ROUGHNESS));
        float hi = (fminf(fmaxf(rough, MAX_ROUGHNESS), 1.0f) - MAX_ROUGHNESS)
                   * (1.0f / (1.0f - MAX_ROUGHNESS)) + (L - 2.0f);
        mip = (rough < MAX_ROUGHNESS) ? lo : hi;
        mip = fminf(fmaxf(mip, 0.0f), L - 1.0f);
    }

    int sface; float su, sv;
    cube_face_uv(rx, ry, rz, sface, su, sv);

    int l0 = (int)floorf(mip);
    if (l0 > N_MIPS - 1) l0 = N_MIPS - 1;
    float f = mip - (float)l0;
    int l1 = l0 + 1;
    if (l1 > N_MIPS - 1) l1 = N_MIPS - 1;

    const float* t0 = specs.p[l0];
    const float* t1 = specs.p[l1];
    int R0 = 512 >> l0;
    int R1 = 512 >> l1;

    float3x s0 = cube_sample_bilinear(t0, R0, sface, su, sv);
    float3x s1 = cube_sample_bilinear(t1, R1, sface, su, sv);

    float spx = (1.0f - f) * s0.x + f * s1.x;
    float spy = (1.0f - f) * s0.y + f * s1.y;
    float spz = (1.0f - f) * s0.z + f * s1.z;

    float refx = sax * fg0 + fg1;
    float refy = say * fg0 + fg1;
    float refz = saz * fg0 + fg1;

    float cx = fminf(fmaxf(spx * refx + dlx, 0.0f), 1.0f);
    float cy = fminf(fmaxf(spy * refy + dly, 0.0f), 1.0f);
    float cz = fminf(fmaxf(spz * refz + dlz, 0.0f), 1.0f);

    ox = linear2srgb(cx);
    oy = linear2srgb(cy);
    oz = linear2srgb(cz);
}

__global__ void __launch_bounds__(256)
envlight_kernel4(const float* __restrict__ gb_pos,
                 const float* __restrict__ gb_normal,
                 const float* __restrict__ basecolor,
                 const float* __restrict__ metallic,
                 const float* __restrict__ roughness,
                 const float* __restrict__ view_pos,
                 const float* __restrict__ diffuse_cube,
                 const float* __restrict__ fg_lut,
                 SpecTable specs,
                 float* __restrict__ out,
                 int n) {
    int q = blockIdx.x * blockDim.x + threadIdx.x;
    int base = q * 4;
    if (base >= n) return;

    float vx = __ldg(view_pos + 0);
    float vy = __ldg(view_pos + 1);
    float vz = __ldg(view_pos + 2);

    float P[12], N[12], BC[12], MET[4], RGH[4];
    bool full = (base + 4 <= n);

    if (full) {
        const float4* p4 = (const float4*)gb_pos + q * 3;
        const float4* n4 = (const float4*)gb_normal + q * 3;
        const float4* b4 = (const float4*)basecolor + q * 3;
        #pragma unroll
        for (int k = 0; k < 3; k++) {
            float4 a = __ldg(p4 + k);
            P[k * 4 + 0] = a.x; P[k * 4 + 1] = a.y; P[k * 4 + 2] = a.z; P[k * 4 + 3] = a.w;
            float4 b = __ldg(n4 + k);
            N[k * 4 + 0] = b.x; N[k * 4 + 1] = b.y; N[k * 4 + 2] = b.z; N[k * 4 + 3] = b.w;
            float4 c = __ldg(b4 + k);
            BC[k * 4 + 0] = c.x; BC[k * 4 + 1] = c.y; BC[k * 4 + 2] = c.z; BC[k * 4 + 3] = c.w;
        }
        float4 m = __ldg((const float4*)metallic + q);
        MET[0] = m.x; MET[1] = m.y; MET[2] = m.z; MET[3] = m.w;
        float4 r = __ldg((const float4*)roughness + q);
        RGH[0] = r.x; RGH[1] = r.y; RGH[2] = r.z; RGH[3] = r.w;
    } else {
        #pragma unroll
        for (int k = 0; k < 4; k++) {
            int i = base + k;
            int ii = (i < n) ? i : (n - 1);
            P[3 * k + 0] = gb_pos[ii * 3 + 0];
            P[3 * k + 1] = gb_pos[ii * 3 + 1];
            P[3 * k + 2] = gb_pos[ii * 3 + 2];
            N[3 * k + 0] = gb_normal[ii * 3 + 0];
            N[3 * k + 1] = gb_normal[ii * 3 + 1];
            N[3 * k + 2] = gb_normal[ii * 3 + 2];
            BC[3 * k + 0] = basecolor[ii * 3 + 0];
            BC[3 * k + 1] = basecolor[ii * 3 + 1];
            BC[3 * k + 2] = basecolor[ii * 3 + 2];
            MET[k] = metallic[ii];
            RGH[k] = roughness[ii];
        }
    }

    float O[12];
    #pragma unroll
    for (int k = 0; k < 4; k++) {
        float ox, oy, oz;
        shade_pixel(P[3 * k + 0], P[3 * k + 1], P[3 * k + 2],
                    N[3 * k + 0], N[3 * k + 1], N[3 * k + 2],
                    BC[3 * k + 0], BC[3 * k + 1], BC[3 * k + 2],
                    MET[k], RGH[k], vx, vy, vz,
                    diffuse_cube, fg_lut, specs, ox, oy, oz);
        O[3 * k + 0] = ox; O[3 * k + 1] = oy; O[3 * k + 2] = oz;
    }

    if (full) {
        float4* o4 = (float4*)out + q * 3;
        #pragma unroll
        for (int k = 0; k < 3; k++) {
            float4 w;
            w.x = O[k * 4 + 0]; w.y = O[k * 4 + 1]; w.z = O[k * 4 + 2]; w.w = O[k * 4 + 3];
            o4[k] = w;
        }
    } else {
        #pragma unroll
        for (int k = 0; k < 4; k++) {
            int i = base + k;
            if (i < n) {
                out[i * 3 + 0] = O[3 * k + 0];
                out[i * 3 + 1] = O[3 * k + 1];
                out[i * 3 + 2] = O[3 * k + 2];
            }
        }
    }
}

extern "C" void kernel_launch(void* const* d_in, const int* in_sizes, int n_in,
                              void* d_out, int out_size) {
    const float* gb_pos    = (const float*)d_in[0];
    const float* gb_normal = (const float*)d_in[1];
    const float* basecolor = (const float*)d_in[2];
    const float* metallic  = (const float*)d_in[3];
    const float* roughness = (const float*)d_in[4];
    const float* view_pos  = (const float*)d_in[5];
    const float* diffuse   = (const float*)d_in[6];
    const float* fg_lut    = (const float*)d_in[7];

    SpecTable specs;
    specs.p[0] = (const float*)d_in[8];
    specs.p[1] = (const float*)d_in[9];
    specs.p[2] = (const float*)d_in[10];
    specs.p[3] = (const float*)d_in[11];
    specs.p[4] = (const float*)d_in[12];
    specs.p[5] = (const float*)d_in[13];

    float* out = (float*)d_out;
    int n = in_sizes[0] / 3;

    int threads = 256;
    int quads = (n + 3) / 4;
    int blocks = (quads + threads - 1) / threads;
    envlight_kernel4<<<blocks, threads>>>(gb_pos, gb_normal, basecolor, metallic,
                                          roughness, view_pos, diffuse, fg_lut,
                                          specs, out, n);
}

// round 5
// speedup vs baseline: 1.3033x; 1.2213x over previous
#include <cuda_runtime.h>
#include <cuda_fp16.h>
#include <math.h>

#define MIN_ROUGHNESS 0.08f
#define MAX_ROUGHNESS 0.5f
#define N_MIPS 6

// Spec mip texel counts (6 faces each): 512,256,128,64,32,16
#define SPEC_TOTAL_TEXELS 2096640
#define DIFF_TEXELS 1536

__constant__ int SPEC_OFF[7] = {0, 1572864, 1966080, 2064384, 2088960, 2095104, 2096640};

// half4 per texel: .x = half2(r,g), .y = half2(b,0)
__device__ __align__(16) uint2 g_spec[SPEC_TOTAL_TEXELS];
__device__ float4 g_diff4[DIFF_TEXELS];

struct SpecTable {
    const float* p[N_MIPS];
};

struct float3x { float x, y, z; };

// ---------------------------------------------------------------------------
// Preprocess: RGB fp32 -> RGBA fp16 (spec mips), RGB fp32 -> RGBA fp32 (diffuse)
// 4 texels per thread.
// ---------------------------------------------------------------------------
__global__ void __launch_bounds__(256)
convert_kernel(SpecTable specs, const float* __restrict__ diffuse) {
    const int quads_spec = SPEC_TOTAL_TEXELS / 4;          // 524160
    const int quads_total = quads_spec + DIFF_TEXELS / 4;  // +384
    int q = blockIdx.x * blockDim.x + threadIdx.x;
    if (q >= quads_total) return;

    if (q < quads_spec) {
        int t = q * 4;
        int lvl = 0;
        if (t >= 1572864) lvl = 1;
        if (t >= 1966080) lvl = 2;
        if (t >= 2064384) lvl = 3;
        if (t >= 2088960) lvl = 4;
        if (t >= 2095104) lvl = 5;
        const float* in = specs.p[lvl] + (size_t)(t - SPEC_OFF[lvl]) * 3;

        float4 a = __ldg((const float4*)in + 0);
        float4 b = __ldg((const float4*)in + 1);
        float4 c = __ldg((const float4*)in + 2);

        __half2 h0a = __floats2half2_rn(a.x, a.y), h0b = __floats2half2_rn(a.z, 0.0f);
        __half2 h1a = __floats2half2_rn(a.w, b.x), h1b = __floats2half2_rn(b.y, 0.0f);
        __half2 h2a = __floats2half2_rn(b.z, b.w), h2b = __floats2half2_rn(c.x, 0.0f);
        __half2 h3a = __floats2half2_rn(c.y, c.z), h3b = __floats2half2_rn(c.w, 0.0f);

        uint4* o = reinterpret_cast<uint4*>(g_spec + t);
        uint4 w0, w1;
        w0.x = *reinterpret_cast<unsigned int*>(&h0a);
        w0.y = *reinterpret_cast<unsigned int*>(&h0b);
        w0.z = *reinterpret_cast<unsigned int*>(&h1a);
        w0.w = *reinterpret_cast<unsigned int*>(&h1b);
        w1.x = *reinterpret_cast<unsigned int*>(&h2a);
        w1.y = *reinterpret_cast<unsigned int*>(&h2b);
        w1.z = *reinterpret_cast<unsigned int*>(&h3a);
        w1.w = *reinterpret_cast<unsigned int*>(&h3b);
        o[0] = w0;
        o[1] = w1;
    } else {
        int t = (q - quads_spec) * 4;
        const float* in = diffuse + (size_t)t * 3;
        float4 a = __ldg((const float4*)in + 0);
        float4 b = __ldg((const float4*)in + 1);
        float4 c = __ldg((const float4*)in + 2);
        g_diff4[t + 0] = make_float4(a.x, a.y, a.z, 0.0f);
        g_diff4[t + 1] = make_float4(a.w, b.x, b.y, 0.0f);
        g_diff4[t + 2] = make_float4(b.z, b.w, c.x, 0.0f);
        g_diff4[t + 3] = make_float4(c.y, c.z, c.w, 0.0f);
    }
}

// ---------------------------------------------------------------------------
// Main shading kernel
// ---------------------------------------------------------------------------

// Scale-invariant: vector need NOT be normalized.
__device__ __forceinline__ void cube_face_uv(float x, float y, float z,
                                             int& face, float& u, float& v) {
    float ax = fabsf(x), ay = fabsf(y), az = fabsf(z);
    bool is_x = (ax >= ay) && (ax >= az);
    bool is_y = (!is_x) && (ay >= az);
    face = is_x ? (x >= 0.0f ? 0 : 1)
                : (is_y ? (y >= 0.0f ? 2 : 3)
                        : (z >= 0.0f ? 4 : 5));
    float ma = fmaxf(is_x ? ax : (is_y ? ay : az), 1e-20f);
    float un = (face == 0) ? -z : (face == 1) ? z : (face == 5) ? -x : x;
    float vn = (face == 2) ? z : (face == 3) ? -z : -y;
    float inv = __fdividef(1.0f, ma);
    u = un * inv;
    v = vn * inv;
}

__device__ __forceinline__ void bilinear_setup(int R, float u, float v,
                                               int& x0, int& x1, int& y0, int& y1,
                                               float& w00, float& w01, float& w10, float& w11) {
    float Rf = (float)R;
    float tu = fmaf(u, 0.5f * Rf, 0.5f * Rf - 0.5f);
    float tv = fmaf(v, 0.5f * Rf, 0.5f * Rf - 0.5f);
    float x0f = floorf(tu);
    float y0f = floorf(tv);
    float fx = tu - x0f;
    float fy = tv - y0f;
    x0 = (int)fminf(fmaxf(x0f, 0.0f), Rf - 1.0f);
    x1 = (int)fminf(fmaxf(x0f + 1.0f, 0.0f), Rf - 1.0f);
    y0 = (int)fminf(fmaxf(y0f, 0.0f), Rf - 1.0f);
    y1 = (int)fminf(fmaxf(y0f + 1.0f, 0.0f), Rf - 1.0f);
    w00 = (1.0f - fx) * (1.0f - fy);
    w01 = fx * (1.0f - fy);
    w10 = (1.0f - fx) * fy;
    w11 = fx * fy;
}

__device__ __forceinline__ float3x cube_bilinear_h(const uint2* __restrict__ tex,
                                                   int R, int face, float u, float v) {
    int x0, x1, y0, y1; float w00, w01, w10, w11;
    bilinear_setup(R, u, v, x0, x1, y0, y1, w00, w01, w10, w11);
    int baseF = face * R * R;
    uint2 r00 = __ldg(tex + baseF + y0 * R + x0);
    uint2 r01 = __ldg(tex + baseF + y0 * R + x1);
    uint2 r10 = __ldg(tex + baseF + y1 * R + x0);
    uint2 r11 = __ldg(tex + baseF + y1 * R + x1);

    float2 a00 = __half22float2(*reinterpret_cast<const __half2*>(&r00.x));
    float2 a01 = __half22float2(*reinterpret_cast<const __half2*>(&r01.x));
    float2 a10 = __half22float2(*reinterpret_cast<const __half2*>(&r10.x));
    float2 a11 = __half22float2(*reinterpret_cast<const __half2*>(&r11.x));
    float b00 = __low2float(*reinterpret_cast<const __half2*>(&r00.y));
    float b01 = __low2float(*reinterpret_cast<const __half2*>(&r01.y));
    float b10 = __low2float(*reinterpret_cast<const __half2*>(&r10.y));
    float b11 = __low2float(*reinterpret_cast<const __half2*>(&r11.y));

    float3x r;
    r.x = a00.x * w00 + a01.x * w01 + a10.x * w10 + a11.x * w11;
    r.y = a00.y * w00 + a01.y * w01 + a10.y * w10 + a11.y * w11;
    r.z = b00 * w00 + b01 * w01 + b10 * w10 + b11 * w11;
    return r;
}

__device__ __forceinline__ float3x cube_bilinear4(const float4* __restrict__ tex,
                                                  int R, int face, float u, float v) {
    int x0, x1, y0, y1; float w00, w01, w10, w11;
    bilinear_setup(R, u, v, x0, x1, y0, y1, w00, w01, w10, w11);
    int baseF = face * R * R;
    float4 c00 = __ldg(tex + baseF + y0 * R + x0);
    float4 c01 = __ldg(tex + baseF + y0 * R + x1);
    float4 c10 = __ldg(tex + baseF + y1 * R + x0);
    float4 c11 = __ldg(tex + baseF + y1 * R + x1);
    float3x r;
    r.x = c00.x * w00 + c01.x * w01 + c10.x * w10 + c11.x * w11;
    r.y = c00.y * w00 + c01.y * w01 + c10.y * w10 + c11.y * w11;
    r.z = c00.z * w00 + c01.z * w01 + c10.z * w10 + c11.z * w11;
    return r;
}

// x^(1/2.4) via MUFU.LG2 + polynomial exp2.
__device__ __forceinline__ float linear2srgb(float x) {
    float l = __log2f(x);
    float y = l * (1.0f / 2.4f);
    float fl = floorf(y);
    float t = y - fl;
    float p = fmaf(t,
              fmaf(t,
              fmaf(t,
              fmaf(t,
              fmaf(t, 0.0013333558f, 0.0096181291f),
                       0.0555041087f),
                       0.2402265070f),
                       0.6931471806f),
                       1.0f);
    int e = (int)fl;
    float r = __int_as_float(__float_as_int(p) + (e << 23));
    float hi = fmaf(1.055f, r, -0.055f);
    return (x > 0.0031308f) ? hi : 12.92f * x;
}

__device__ __forceinline__ void shade_pixel(
    float px, float py, float pz,
    float nx, float ny, float nz,
    float bcx, float bcy, float bcz,
    float met, float rough,
    float vx, float vy, float vz,
    const float* __restrict__ fg_lut,
    float& ox, float& oy, float& oz)
{
    // wo left unnormalized; NdotV computed with rsqrt; reflvec is
    // scale-invariant in wo and feeds only cube_face_uv (scale-invariant).
    float wx = vx - px, wy = vy - py, wz = vz - pz;
    float wlen2 = fmaxf(wx * wx + wy * wy + wz * wz, 1e-20f);
    float winv = rsqrtf(wlen2);

    float om = 1.0f - met;
    float dax = om * bcx, day = om * bcy, daz = om * bcz;
    float sax = 0.04f * om + met * bcx;
    float say = 0.04f * om + met * bcy;
    float saz = 0.04f * om + met * bcz;

    float d_un = wx * nx + wy * ny + wz * nz;      // dot with unnormalized wo
    float rx = 2.0f * d_un * nx - wx;
    float ry = 2.0f * d_un * ny - wy;
    float rz = 2.0f * d_un * nz - wz;

    // ambient from diffuse cubemap (16^2, float4)
    int dface; float du, dv;
    cube_face_uv(nx, ny, nz, dface, du, dv);
    float3x ambient = cube_bilinear4(g_diff4, 16, dface, du, dv);

    float dlx = ambient.x * dax;
    float dly = ambient.y * day;
    float dlz = ambient.z * daz;

    // FG LUT (256x256x2, clamp)
    float NdotV = fmaxf(d_un * winv, 0.0001f);
    float fg0, fg1;
    {
        float tu = NdotV * 256.0f - 0.5f;
        float tv = rough * 256.0f - 0.5f;
        float x0f = floorf(tu);
        float y0f = floorf(tv);
        float fx = tu - x0f;
        float fy = tv - y0f;
        int x0 = (int)fminf(fmaxf(x0f, 0.0f), 255.0f);
        int x1 = (int)fminf(fmaxf(x0f + 1.0f, 0.0f), 255.0f);
        int y0 = (int)fminf(fmaxf(y0f, 0.0f), 255.0f);
        int y1 = (int)fminf(fmaxf(y0f + 1.0f, 0.0f), 255.0f);
        float w00 = (1.0f - fx) * (1.0f - fy);
        float w01 = fx * (1.0f - fy);
        float w10 = (1.0f - fx) * fy;
        float w11 = fx * fy;
        float2 c00 = __ldg((const float2*)fg_lut + (y0 * 256 + x0));
        float2 c01 = __ldg((const float2*)fg_lut + (y0 * 256 + x1));
        float2 c10 = __ldg((const float2*)fg_lut + (y1 * 256 + x0));
        float2 c11 = __ldg((const float2*)fg_lut + (y1 * 256 + x1));
        fg0 = c00.x * w00 + c01.x * w01 + c10.x * w10 + c11.x * w11;
        fg1 = c00.y * w00 + c01.y * w01 + c10.y * w10 + c11.y * w11;
    }

    // mip
    float mip;
    {
        const float L = (float)N_MIPS;
        float lo = (fminf(fmaxf(rough, MIN_ROUGHNESS), MAX_ROUGHNESS) - MIN_ROUGHNESS)
                   * ((L - 2.0f) / (MAX_ROUGHNESS - MIN_ROUGHNESS));
        float hi = (fminf(fmaxf(rough, MAX_ROUGHNESS), 1.0f) - MAX_ROUGHNESS)
                   * (1.0f / (1.0f - MAX_ROUGHNESS)) + (L - 2.0f);
        mip = (rough < MAX_ROUGHNESS) ? lo : hi;
        mip = fminf(fmaxf(mip, 0.0f), L - 1.0f);
    }

    int sface; float su, sv;
    cube_face_uv(rx, ry, rz, sface, su, sv);

    int l0 = (int)floorf(mip);
    if (l0 > N_MIPS - 1) l0 = N_MIPS - 1;
    float f = mip - (float)l0;
    int l1 = l0 + 1;
    if (l1 > N_MIPS - 1) l1 = N_MIPS - 1;

    const uint2* t0 = g_spec + SPEC_OFF[l0];
    const uint2* t1 = g_spec + SPEC_OFF[l1];
    int R0 = 512 >> l0;
    int R1 = 512 >> l1;

    float3x s0 = cube_bilinear_h(t0, R0, sface, su, sv);
    float3x s1 = cube_bilinear_h(t1, R1, sface, su, sv);

    float spx = (1.0f - f) * s0.x + f * s1.x;
    float spy = (1.0f - f) * s0.y + f * s1.y;
    float spz = (1.0f - f) * s0.z + f * s1.z;

    float refx = sax * fg0 + fg1;
    float refy = say * fg0 + fg1;
    float refz = saz * fg0 + fg1;

    float cx = fminf(fmaxf(spx * refx + dlx, 0.0f), 1.0f);
    float cy = fminf(fmaxf(spy * refy + dly, 0.0f), 1.0f);
    float cz = fminf(fmaxf(spz * refz + dlz, 0.0f), 1.0f);

    ox = linear2srgb(cx);
    oy = linear2srgb(cy);
    oz = linear2srgb(cz);
}

__global__ void __launch_bounds__(256, 4)
envlight_kernel2(const float* __restrict__ gb_pos,
                 const float* __restrict__ gb_normal,
                 const float* __restrict__ basecolor,
                 const float* __restrict__ metallic,
                 const float* __restrict__ roughness,
                 const float* __restrict__ view_pos,
                 const float* __restrict__ fg_lut,
                 float* __restrict__ out,
                 int n) {
    int q = blockIdx.x * blockDim.x + threadIdx.x;
    int base = q * 2;
    if (base >= n) return;

    float vx = __ldg(view_pos + 0);
    float vy = __ldg(view_pos + 1);
    float vz = __ldg(view_pos + 2);

    float P[6], N[6], BC[6], MET[2], RGH[2];
    bool full = (base + 2 <= n);

    if (full) {
        const float2* p2 = (const float2*)gb_pos + q * 3;
        const float2* n2 = (const float2*)gb_normal + q * 3;
        const float2* b2 = (const float2*)basecolor + q * 3;
        #pragma unroll
        for (int k = 0; k < 3; k++) {
            float2 a = __ldg(p2 + k);
            P[k * 2 + 0] = a.x; P[k * 2 + 1] = a.y;
            float2 b = __ldg(n2 + k);
            N[k * 2 + 0] = b.x; N[k * 2 + 1] = b.y;
            float2 c = __ldg(b2 + k);
            BC[k * 2 + 0] = c.x; BC[k * 2 + 1] = c.y;
        }
        float2 m = __ldg((const float2*)metallic + q);
        MET[0] = m.x; MET[1] = m.y;
        float2 r = __ldg((const float2*)roughness + q);
        RGH[0] = r.x; RGH[1] = r.y;
    } else {
        #pragma unroll
        for (int k = 0; k < 2; k++) {
            int i = base + k;
            int ii = (i < n) ? i : (n - 1);
            P[3 * k + 0] = gb_pos[ii * 3 + 0];
            P[3 * k + 1] = gb_pos[ii * 3 + 1];
            P[3 * k + 2] = gb_pos[ii * 3 + 2];
            N[3 * k + 0] = gb_normal[ii * 3 + 0];
            N[3 * k + 1] = gb_normal[ii * 3 + 1];
            N[3 * k + 2] = gb_normal[ii * 3 + 2];
            BC[3 * k + 0] = basecolor[ii * 3 + 0];
            BC[3 * k + 1] = basecolor[ii * 3 + 1];
            BC[3 * k + 2] = basecolor[ii * 3 + 2];
            MET[k] = metallic[ii];
            RGH[k] = roughness[ii];
        }
    }

    float O[6];
    #pragma unroll
    for (int k = 0; k < 2; k++) {
        float ox, oy, oz;
        shade_pixel(P[3 * k + 0], P[3 * k + 1], P[3 * k + 2],
                    N[3 * k + 0], N[3 * k + 1], N[3 * k + 2],
                    BC[3 * k + 0], BC[3 * k + 1], BC[3 * k + 2],
                    MET[k], RGH[k], vx, vy, vz,
                    fg_lut, ox, oy, oz);
        O[3 * k + 0] = ox; O[3 * k + 1] = oy; O[3 * k + 2] = oz;
    }

    if (full) {
        float2* o2 = (float2*)out + q * 3;
        o2[0] = make_float2(O[0], O[1]);
        o2[1] = make_float2(O[2], O[3]);
        o2[2] = make_float2(O[4], O[5]);
    } else {
        #pragma unroll
        for (int k = 0; k < 2; k++) {
            int i = base + k;
            if (i < n) {
                out[i * 3 + 0] = O[3 * k + 0];
                out[i * 3 + 1] = O[3 * k + 1];
                out[i * 3 + 2] = O[3 * k + 2];
            }
        }
    }
}

extern "C" void kernel_launch(void* const* d_in, const int* in_sizes, int n_in,
                              void* d_out, int out_size) {
    const float* gb_pos    = (const float*)d_in[0];
    const float* gb_normal = (const float*)d_in[1];
    const float* basecolor = (const float*)d_in[2];
    const float* metallic  = (const float*)d_in[3];
    const float* roughness = (const float*)d_in[4];
    const float* view_pos  = (const float*)d_in[5];
    const float* diffuse   = (const float*)d_in[6];
    const float* fg_lut    = (const float*)d_in[7];

    SpecTable specs;
    specs.p[0] = (const float*)d_in[8];
    specs.p[1] = (const float*)d_in[9];
    specs.p[2] = (const float*)d_in[10];
    specs.p[3] = (const float*)d_in[11];
    specs.p[4] = (const float*)d_in[12];
    specs.p[5] = (const float*)d_in[13];

    float* out = (float*)d_out;
    int n = in_sizes[0] / 3;

    // Pass 1: repack RGB -> fp16 RGBA (spec) + fp32 RGBA (diffuse)
    {
        int quads_total = SPEC_TOTAL_TEXELS / 4 + DIFF_TEXELS / 4;
        int threads = 256;
        int blocks = (quads_total + threads - 1) / threads;
        convert_kernel<<<blocks, threads>>>(specs, diffuse);
    }

    // Pass 2: shade, 2 px/thread
    {
        int threads = 256;
        int pairs = (n + 1) / 2;
        int blocks = (pairs + threads - 1) / threads;
        envlight_kernel2<<<blocks, threads>>>(gb_pos, gb_normal, basecolor, metallic,
                                              roughness, view_pos, fg_lut, out, n);
    }
}

// round 6
// speedup vs baseline: 1.3541x; 1.0390x over previous
#include <cuda_runtime.h>
#include <cuda_fp16.h>
#include <math.h>

#define MIN_ROUGHNESS 0.08f
#define MAX_ROUGHNESS 0.5f
#define N_MIPS 6

#define SPEC_TOTAL_TEXELS 2096640
#define DIFF_TEXELS 1536
#define FG_TEXELS 65536

__constant__ int SPEC_OFF[7] = {0, 1572864, 1966080, 2064384, 2088960, 2095104, 2096640};

// Paired-texel records: entry x holds texels x and x+1 (x+1 clamped at row end).
__device__ uint4  g_spec[SPEC_TOTAL_TEXELS];  // fp16 rgb|rgb (33.5 MB)
__device__ uint4  g_diff[DIFF_TEXELS];        // fp16 rgb|rgb (24 KB)
__device__ float4 g_fg[FG_TEXELS];            // fp32 (fg0,fg1)|(fg0,fg1) (1 MB)

struct SpecTable {
    const float* p[N_MIPS];
};

struct float3x { float x, y, z; };

// ---------------------------------------------------------------------------
// Repack pass
// ---------------------------------------------------------------------------
__device__ __forceinline__ uint4 pack_pair(float lr, float lg, float lb,
                                           float hr, float hg, float hb) {
    __half2 A = __floats2half2_rn(lr, lg);
    __half2 B = __floats2half2_rn(lb, hr);
    __half2 C = __floats2half2_rn(hg, hb);
    uint4 o;
    o.x = *reinterpret_cast<unsigned int*>(&A);
    o.y = *reinterpret_cast<unsigned int*>(&B);
    o.z = *reinterpret_cast<unsigned int*>(&C);
    o.w = 0u;
    return o;
}

// Repack 4 consecutive texels (one chunk) of an RGB fp32 texture into paired
// fp16 records. local = first texel idx (multiple of 4), R = row width (mult of 4).
__device__ __forceinline__ void repack_rgb_chunk(const float* __restrict__ in,
                                                 uint4* __restrict__ out,
                                                 int local, int R) {
    int x = local % R;
    const float4* p = (const float4*)(in + (size_t)local * 3);
    float4 a = __ldg(p + 0);
    float4 b = __ldg(p + 1);
    float4 c = __ldg(p + 2);
    float f[16];
    f[0] = a.x; f[1] = a.y; f[2]  = a.z; f[3]  = a.w;
    f[4] = b.x; f[5] = b.y; f[6]  = b.z; f[7]  = b.w;
    f[8] = c.x; f[9] = c.y; f[10] = c.z; f[11] = c.w;
    bool has_next = (x + 4 < R);
    if (has_next) {
        float4 d = __ldg(p + 3);
        f[12] = d.x; f[13] = d.y; f[14] = d.z; f[15] = d.w;
    } else {
        f[12] = f[9]; f[13] = f[10]; f[14] = f[11]; f[15] = 0.0f; // dup texel x+3
    }
    #pragma unroll
    for (int i = 0; i < 4; i++) {
        float lr = f[3 * i + 0], lg = f[3 * i + 1], lb = f[3 * i + 2];
        float hr = f[3 * i + 3], hg = f[3 * i + 4], hb = f[3 * i + 5];
        out[local + i] = pack_pair(lr, lg, lb, hr, hg, hb);
    }
}

__global__ void __launch_bounds__(256)
repack_kernel(SpecTable specs, const float* __restrict__ diffuse,
              const float* __restrict__ fg_lut) {
    const int QS = SPEC_TOTAL_TEXELS / 4;   // 524160
    const int QD = QS + DIFF_TEXELS / 4;    // 524544
    const int QF = QD + FG_TEXELS / 4;      // 540928
    int q = blockIdx.x * blockDim.x + threadIdx.x;
    if (q >= QF) return;

    if (q < QS) {
        int t = q * 4;
        int lvl = 0;
        if (t >= 1572864) lvl = 1;
        if (t >= 1966080) lvl = 2;
        if (t >= 2064384) lvl = 3;
        if (t >= 2088960) lvl = 4;
        if (t >= 2095104) lvl = 5;
        int local = t - SPEC_OFF[lvl];
        repack_rgb_chunk(specs.p[lvl], g_spec + SPEC_OFF[lvl], local, 512 >> lvl);
    } else if (q < QD) {
        int local = (q - QS) * 4;
        repack_rgb_chunk(diffuse, g_diff, local, 16);
    } else {
        int t = (q - QD) * 4;
        int x = t % 256;
        const float4* p = (const float4*)(fg_lut + (size_t)t * 2);
        float4 a = __ldg(p + 0);
        float4 b = __ldg(p + 1);
        float f[12];
        f[0] = a.x; f[1] = a.y; f[2] = a.z; f[3] = a.w;
        f[4] = b.x; f[5] = b.y; f[6] = b.z; f[7] = b.w;
        bool has_next = (x + 4 < 256);
        if (has_next) {
            float4 c = __ldg(p + 2);
            f[8] = c.x; f[9] = c.y; f[10] = c.z; f[11] = c.w;
        } else {
            f[8] = f[6]; f[9] = f[7]; f[10] = 0.0f; f[11] = 0.0f; // dup texel x+3
        }
        #pragma unroll
        for (int i = 0; i < 4; i++) {
            g_fg[t + i] = make_float4(f[2 * i + 0], f[2 * i + 1],
                                      f[2 * i + 2], f[2 * i + 3]);
        }
    }
}

// ---------------------------------------------------------------------------
// Main shading kernel
// ---------------------------------------------------------------------------

// Scale-invariant cube face/uv (vector need not be normalized).
__device__ __forceinline__ void cube_face_uv(float x, float y, float z,
                                             int& face, float& u, float& v) {
    float ax = fabsf(x), ay = fabsf(y), az = fabsf(z);
    bool is_x = (ax >= ay) && (ax >= az);
    bool is_y = (!is_x) && (ay >= az);
    face = is_x ? (x >= 0.0f ? 0 : 1)
                : (is_y ? (y >= 0.0f ? 2 : 3)
                        : (z >= 0.0f ? 4 : 5));
    float ma = fmaxf(is_x ? ax : (is_y ? ay : az), 1e-20f);
    float un = (face == 0) ? -z : (face == 1) ? z : (face == 5) ? -x : x;
    float vn = (face == 2) ? z : (face == 3) ? -z : -y;
    float inv = __fdividef(1.0f, ma);
    u = un * inv;
    v = vn * inv;
}

// Setup for paired-texel bilinear. fx forced to 0 at left edge (ref clamps
// both x-taps to texel 0 there); right edge self-duplicates in the record.
__device__ __forceinline__ void pair_setup(float Rf, float tu, float tv,
                                           int& x0, int& y0, int& y1,
                                           float& fx, float& fy) {
    float x0f = floorf(tu);
    float y0f = floorf(tv);
    fx = tu - x0f;
    if (x0f < 0.0f) fx = 0.0f;
    fy = tv - y0f;
    x0 = (int)fminf(fmaxf(x0f, 0.0f), Rf - 1.0f);
    y0 = (int)fminf(fmaxf(y0f, 0.0f), Rf - 1.0f);
    y1 = (int)fminf(fmaxf(y0f + 1.0f, 0.0f), Rf - 1.0f);
}

__device__ __forceinline__ float3x cube_bilinear_pair(const uint4* __restrict__ tex,
                                                      int R, int face,
                                                      float u, float v) {
    float Rf = (float)R;
    float tu = fmaf(u, 0.5f * Rf, 0.5f * Rf - 0.5f);
    float tv = fmaf(v, 0.5f * Rf, 0.5f * Rf - 0.5f);
    int x0, y0, y1; float fx, fy;
    pair_setup(Rf, tu, tv, x0, y0, y1, fx, fy);

    int base = face * R * R + x0;
    uint4 e0 = __ldg(tex + base + y0 * R);
    uint4 e1 = __ldg(tex + base + y1 * R);

    float2 A0 = __half22float2(*reinterpret_cast<const __half2*>(&e0.x));
    float2 B0 = __half22float2(*reinterpret_cast<const __half2*>(&e0.y));
    float2 C0 = __half22float2(*reinterpret_cast<const __half2*>(&e0.z));
    float2 A1 = __half22float2(*reinterpret_cast<const __half2*>(&e1.x));
    float2 B1 = __half22float2(*reinterpret_cast<const __half2*>(&e1.y));
    float2 C1 = __half22float2(*reinterpret_cast<const __half2*>(&e1.z));

    // row lerps in x
    float r0 = A0.x + fx * (B0.y - A0.x);
    float g0 = A0.y + fx * (C0.x - A0.y);
    float b0 = B0.x + fx * (C0.y - B0.x);
    float r1 = A1.x + fx * (B1.y - A1.x);
    float g1 = A1.y + fx * (C1.x - A1.y);
    float b1 = B1.x + fx * (C1.y - B1.x);

    float3x r;
    r.x = r0 + fy * (r1 - r0);
    r.y = g0 + fy * (g1 - g0);
    r.z = b0 + fy * (b1 - b0);
    return r;
}

// x^(1/2.4) via MUFU.LG2 + polynomial exp2.
__device__ __forceinline__ float linear2srgb(float x) {
    float l = __log2f(x);
    float y = l * (1.0f / 2.4f);
    float fl = floorf(y);
    float t = y - fl;
    float p = fmaf(t,
              fmaf(t,
              fmaf(t,
              fmaf(t,
              fmaf(t, 0.0013333558f, 0.0096181291f),
                       0.0555041087f),
                       0.2402265070f),
                       0.6931471806f),
                       1.0f);
    int e = (int)fl;
    float r = __int_as_float(__float_as_int(p) + (e << 23));
    float hi = fmaf(1.055f, r, -0.055f);
    return (x > 0.0031308f) ? hi : 12.92f * x;
}

__device__ __forceinline__ void shade_pixel(
    float px, float py, float pz,
    float nx, float ny, float nz,
    float bcx, float bcy, float bcz,
    float met, float rough,
    float vx, float vy, float vz,
    float& ox, float& oy, float& oz)
{
    // wo left unnormalized; only NdotV needs the normalization factor.
    float wx = vx - px, wy = vy - py, wz = vz - pz;
    float wlen2 = fmaxf(wx * wx + wy * wy + wz * wz, 1e-20f);
    float winv = rsqrtf(wlen2);

    float om = 1.0f - met;
    float dax = om * bcx, day = om * bcy, daz = om * bcz;
    float sax = 0.04f * om + met * bcx;
    float say = 0.04f * om + met * bcy;
    float saz = 0.04f * om + met * bcz;

    float d_un = wx * nx + wy * ny + wz * nz;
    float rx = 2.0f * d_un * nx - wx;
    float ry = 2.0f * d_un * ny - wy;
    float rz = 2.0f * d_un * nz - wz;

    // ambient from diffuse cubemap (16^2, fp16 pairs)
    int dface; float du, dv;
    cube_face_uv(nx, ny, nz, dface, du, dv);
    float3x ambient = cube_bilinear_pair(g_diff, 16, dface, du, dv);

    float dlx = ambient.x * dax;
    float dly = ambient.y * day;
    float dlz = ambient.z * daz;

    // FG LUT (256x256x2, clamp, fp32 pairs)
    float NdotV = fmaxf(d_un * winv, 0.0001f);
    float fg0, fg1;
    {
        float tu = NdotV * 256.0f - 0.5f;
        float tv = rough * 256.0f - 0.5f;
        int x0, y0, y1; float fx, fy;
        pair_setup(256.0f, tu, tv, x0, y0, y1, fx, fy);
        float4 e0 = __ldg(g_fg + y0 * 256 + x0);
        float4 e1 = __ldg(g_fg + y1 * 256 + x0);
        float a0 = e0.x + fx * (e0.z - e0.x);
        float b0 = e0.y + fx * (e0.w - e0.y);
        float a1 = e1.x + fx * (e1.z - e1.x);
        float b1 = e1.y + fx * (e1.w - e1.y);
        fg0 = a0 + fy * (a1 - a0);
        fg1 = b0 + fy * (b1 - b0);
    }

    // mip
    float mip;
    {
        const float L = (float)N_MIPS;
        float lo = (fminf(fmaxf(rough, MIN_ROUGHNESS), MAX_ROUGHNESS) - MIN_ROUGHNESS)
                   * ((L - 2.0f) / (MAX_ROUGHNESS - MIN_ROUGHNESS));
        float hi = (fminf(fmaxf(rough, MAX_ROUGHNESS), 1.0f) - MAX_ROUGHNESS)
                   * (1.0f / (1.0f - MAX_ROUGHNESS)) + (L - 2.0f);
        mip = (rough < MAX_ROUGHNESS) ? lo : hi;
        mip = fminf(fmaxf(mip, 0.0f), L - 1.0f);
    }

    int sface; float su, sv;
    cube_face_uv(rx, ry, rz, sface, su, sv);

    int l0 = (int)floorf(mip);
    if (l0 > N_MIPS - 1) l0 = N_MIPS - 1;
    float f = mip - (float)l0;
    int l1 = l0 + 1;
    if (l1 > N_MIPS - 1) l1 = N_MIPS - 1;

    const uint4* t0 = g_spec + SPEC_OFF[l0];
    const uint4* t1 = g_spec + SPEC_OFF[l1];
    int R0 = 512 >> l0;
    int R1 = 512 >> l1;

    float3x s0 = cube_bilinear_pair(t0, R0, sface, su, sv);
    float3x s1 = cube_bilinear_pair(t1, R1, sface, su, sv);

    float spx = s0.x + f * (s1.x - s0.x);
    float spy = s0.y + f * (s1.y - s0.y);
    float spz = s0.z + f * (s1.z - s0.z);

    float refx = sax * fg0 + fg1;
    float refy = say * fg0 + fg1;
    float refz = saz * fg0 + fg1;

    float cx = fminf(fmaxf(spx * refx + dlx, 0.0f), 1.0f);
    float cy = fminf(fmaxf(spy * refy + dly, 0.0f), 1.0f);
    float cz = fminf(fmaxf(spz * refz + dlz, 0.0f), 1.0f);

    ox = linear2srgb(cx);
    oy = linear2srgb(cy);
    oz = linear2srgb(cz);
}

__global__ void __launch_bounds__(256, 4)
envlight_kernel2(const float* __restrict__ gb_pos,
                 const float* __restrict__ gb_normal,
                 const float* __restrict__ basecolor,
                 const float* __restrict__ metallic,
                 const float* __restrict__ roughness,
                 const float* __restrict__ view_pos,
                 float* __restrict__ out,
                 int n) {
    int q = blockIdx.x * blockDim.x + threadIdx.x;
    int base = q * 2;
    if (base >= n) return;

    float vx = __ldg(view_pos + 0);
    float vy = __ldg(view_pos + 1);
    float vz = __ldg(view_pos + 2);

    float P[6], N[6], BC[6], MET[2], RGH[2];
    bool full = (base + 2 <= n);

    if (full) {
        const float2* p2 = (const float2*)gb_pos + q * 3;
        const float2* n2 = (const float2*)gb_normal + q * 3;
        const float2* b2 = (const float2*)basecolor + q * 3;
        #pragma unroll
        for (int k = 0; k < 3; k++) {
            float2 a = __ldg(p2 + k);
            P[k * 2 + 0] = a.x; P[k * 2 + 1] = a.y;
            float2 b = __ldg(n2 + k);
            N[k * 2 + 0] = b.x; N[k * 2 + 1] = b.y;
            float2 c = __ldg(b2 + k);
            BC[k * 2 + 0] = c.x; BC[k * 2 + 1] = c.y;
        }
        float2 m = __ldg((const float2*)metallic + q);
        MET[0] = m.x; MET[1] = m.y;
        float2 r = __ldg((const float2*)roughness + q);
        RGH[0] = r.x; RGH[1] = r.y;
    } else {
        #pragma unroll
        for (int k = 0; k < 2; k++) {
            int i = base + k;
            int ii = (i < n) ? i : (n - 1);
            P[3 * k + 0] = gb_pos[ii * 3 + 0];
            P[3 * k + 1] = gb_pos[ii * 3 + 1];
            P[3 * k + 2] = gb_pos[ii * 3 + 2];
            N[3 * k + 0] = gb_normal[ii * 3 + 0];
            N[3 * k + 1] = gb_normal[ii * 3 + 1];
            N[3 * k + 2] = gb_normal[ii * 3 + 2];
            BC[3 * k + 0] = basecolor[ii * 3 + 0];
            BC[3 * k + 1] = basecolor[ii * 3 + 1];
            BC[3 * k + 2] = basecolor[ii * 3 + 2];
            MET[k] = metallic[ii];
            RGH[k] = roughness[ii];
        }
    }

    float O[6];
    #pragma unroll
    for (int k = 0; k < 2; k++) {
        float ox, oy, oz;
        shade_pixel(P[3 * k + 0], P[3 * k + 1], P[3 * k + 2],
                    N[3 * k + 0], N[3 * k + 1], N[3 * k + 2],
                    BC[3 * k + 0], BC[3 * k + 1], BC[3 * k + 2],
                    MET[k], RGH[k], vx, vy, vz,
                    ox, oy, oz);
        O[3 * k + 0] = ox; O[3 * k + 1] = oy; O[3 * k + 2] = oz;
    }

    if (full) {
        float2* o2 = (float2*)out + q * 3;
        o2[0] = make_float2(O[0], O[1]);
        o2[1] = make_float2(O[2], O[3]);
        o2[2] = make_float2(O[4], O[5]);
    } else {
        #pragma unroll
        for (int k = 0; k < 2; k++) {
            int i = base + k;
            if (i < n) {
                out[i * 3 + 0] = O[3 * k + 0];
                out[i * 3 + 1] = O[3 * k + 1];
                out[i * 3 + 2] = O[3 * k + 2];
            }
        }
    }
}

extern "C" void kernel_launch(void* const* d_in, const int* in_sizes, int n_in,
                              void* d_out, int out_size) {
    const float* gb_pos    = (const float*)d_in[0];
    const float* gb_normal = (const float*)d_in[1];
    const float* basecolor = (const float*)d_in[2];
    const float* metallic  = (const float*)d_in[3];
    const float* roughness = (const float*)d_in[4];
    const float* view_pos  = (const float*)d_in[5];
    const float* diffuse   = (const float*)d_in[6];
    const float* fg_lut    = (const float*)d_in[7];

    SpecTable specs;
    specs.p[0] = (const float*)d_in[8];
    specs.p[1] = (const float*)d_in[9];
    specs.p[2] = (const float*)d_in[10];
    specs.p[3] = (const float*)d_in[11];
    specs.p[4] = (const float*)d_in[12];
    specs.p[5] = (const float*)d_in[13];

    float* out = (float*)d_out;
    int n = in_sizes[0] / 3;

    // Pass 1: repack all textures into paired-texel records
    {
        int chunks = SPEC_TOTAL_TEXELS / 4 + DIFF_TEXELS / 4 + FG_TEXELS / 4;
        int threads = 256;
        int blocks = (chunks + threads - 1) / threads;
        repack_kernel<<<blocks, threads>>>(specs, diffuse, fg_lut);
    }

    // Pass 2: shade, 2 px/thread
    {
        int threads = 256;
        int pairs = (n + 1) / 2;
        int blocks = (pairs + threads - 1) / threads;
        envlight_kernel2<<<blocks, threads>>>(gb_pos, gb_normal, basecolor, metallic,
                                              roughness, view_pos, out, n);
    }
}

// round 7
// speedup vs baseline: 1.4536x; 1.0735x over previous
#include <cuda_runtime.h>
#include <cuda_fp16.h>
#include <math.h>

#define MIN_ROUGHNESS 0.08f
#define MAX_ROUGHNESS 0.5f
#define N_MIPS 6

#define SPEC_TOTAL_TEXELS 2096640
#define DIFF_TEXELS 1536
#define FG_TEXELS 65536

__constant__ int SPEC_OFF[7] = {0, 1572864, 1966080, 2064384, 2088960, 2095104, 2096640};

// Paired-texel records: entry x holds texels x and x+1 (x+1 clamped at row end).
__device__ uint4  g_spec[SPEC_TOTAL_TEXELS];  // fp16 rgb|rgb (33.5 MB)
__device__ uint4  g_diff[DIFF_TEXELS];        // fp16 rgb|rgb (24 KB)
__device__ float4 g_fg[FG_TEXELS];            // fp32 (fg0,fg1)|(fg0,fg1) (1 MB)

struct SpecTable {
    const float* p[N_MIPS];
};

struct float3x { float x, y, z; };

// ---------------------------------------------------------------------------
// Repack pass
// ---------------------------------------------------------------------------
__device__ __forceinline__ uint4 pack_pair(float lr, float lg, float lb,
                                           float hr, float hg, float hb) {
    __half2 A = __floats2half2_rn(lr, lg);
    __half2 B = __floats2half2_rn(lb, hr);
    __half2 C = __floats2half2_rn(hg, hb);
    uint4 o;
    o.x = *reinterpret_cast<unsigned int*>(&A);
    o.y = *reinterpret_cast<unsigned int*>(&B);
    o.z = *reinterpret_cast<unsigned int*>(&C);
    o.w = 0u;
    return o;
}

__device__ __forceinline__ void repack_rgb_chunk(const float* __restrict__ in,
                                                 uint4* __restrict__ out,
                                                 int local, int R) {
    int x = local % R;
    const float4* p = (const float4*)(in + (size_t)local * 3);
    float4 a = __ldg(p + 0);
    float4 b = __ldg(p + 1);
    float4 c = __ldg(p + 2);
    float f[16];
    f[0] = a.x; f[1] = a.y; f[2]  = a.z; f[3]  = a.w;
    f[4] = b.x; f[5] = b.y; f[6]  = b.z; f[7]  = b.w;
    f[8] = c.x; f[9] = c.y; f[10] = c.z; f[11] = c.w;
    bool has_next = (x + 4 < R);
    if (has_next) {
        float4 d = __ldg(p + 3);
        f[12] = d.x; f[13] = d.y; f[14] = d.z; f[15] = d.w;
    } else {
        f[12] = f[9]; f[13] = f[10]; f[14] = f[11]; f[15] = 0.0f;
    }
    #pragma unroll
    for (int i = 0; i < 4; i++) {
        out[local + i] = pack_pair(f[3 * i + 0], f[3 * i + 1], f[3 * i + 2],
                                   f[3 * i + 3], f[3 * i + 4], f[3 * i + 5]);
    }
}

__global__ void __launch_bounds__(256)
repack_kernel(SpecTable specs, const float* __restrict__ diffuse,
              const float* __restrict__ fg_lut) {
    const int QS = SPEC_TOTAL_TEXELS / 4;
    const int QD = QS + DIFF_TEXELS / 4;
    const int QF = QD + FG_TEXELS / 4;
    int q = blockIdx.x * blockDim.x + threadIdx.x;
    if (q >= QF) return;

    if (q < QS) {
        int t = q * 4;
        int lvl = 0;
        if (t >= 1572864) lvl = 1;
        if (t >= 1966080) lvl = 2;
        if (t >= 2064384) lvl = 3;
        if (t >= 2088960) lvl = 4;
        if (t >= 2095104) lvl = 5;
        int local = t - SPEC_OFF[lvl];
        repack_rgb_chunk(specs.p[lvl], g_spec + SPEC_OFF[lvl], local, 512 >> lvl);
    } else if (q < QD) {
        int local = (q - QS) * 4;
        repack_rgb_chunk(diffuse, g_diff, local, 16);
    } else {
        int t = (q - QD) * 4;
        int x = t % 256;
        const float4* p = (const float4*)(fg_lut + (size_t)t * 2);
        float4 a = __ldg(p + 0);
        float4 b = __ldg(p + 1);
        float f[12];
        f[0] = a.x; f[1] = a.y; f[2] = a.z; f[3] = a.w;
        f[4] = b.x; f[5] = b.y; f[6] = b.z; f[7] = b.w;
        bool has_next = (x + 4 < 256);
        if (has_next) {
            float4 c = __ldg(p + 2);
            f[8] = c.x; f[9] = c.y; f[10] = c.z; f[11] = c.w;
        } else {
            f[8] = f[6]; f[9] = f[7]; f[10] = 0.0f; f[11] = 0.0f;
        }
        #pragma unroll
        for (int i = 0; i < 4; i++) {
            g_fg[t + i] = make_float4(f[2 * i + 0], f[2 * i + 1],
                                      f[2 * i + 2], f[2 * i + 3]);
        }
    }
}

// ---------------------------------------------------------------------------
// Main shading kernel
// ---------------------------------------------------------------------------
__device__ __forceinline__ void cube_face_uv(float x, float y, float z,
                                             int& face, float& u, float& v) {
    float ax = fabsf(x), ay = fabsf(y), az = fabsf(z);
    bool is_x = (ax >= ay) && (ax >= az);
    bool is_y = (!is_x) && (ay >= az);
    face = is_x ? (x >= 0.0f ? 0 : 1)
                : (is_y ? (y >= 0.0f ? 2 : 3)
                        : (z >= 0.0f ? 4 : 5));
    float ma = fmaxf(is_x ? ax : (is_y ? ay : az), 1e-20f);
    float un = (face == 0) ? -z : (face == 1) ? z : (face == 5) ? -x : x;
    float vn = (face == 2) ? z : (face == 3) ? -z : -y;
    float inv = __fdividef(1.0f, ma);
    u = un * inv;
    v = vn * inv;
}

__device__ __forceinline__ void pair_setup(float Rf, float tu, float tv,
                                           int& x0, int& y0, int& y1,
                                           float& fx, float& fy) {
    float x0f = floorf(tu);
    float y0f = floorf(tv);
    fx = tu - x0f;
    if (x0f < 0.0f) fx = 0.0f;
    fy = tv - y0f;
    x0 = (int)fminf(fmaxf(x0f, 0.0f), Rf - 1.0f);
    y0 = (int)fminf(fmaxf(y0f, 0.0f), Rf - 1.0f);
    y1 = (int)fminf(fmaxf(y0f + 1.0f, 0.0f), Rf - 1.0f);
}

__device__ __forceinline__ float3x cube_bilinear_pair(const uint4* __restrict__ tex,
                                                      int R, int face,
                                                      float u, float v) {
    float Rf = (float)R;
    float tu = fmaf(u, 0.5f * Rf, 0.5f * Rf - 0.5f);
    float tv = fmaf(v, 0.5f * Rf, 0.5f * Rf - 0.5f);
    int x0, y0, y1; float fx, fy;
    pair_setup(Rf, tu, tv, x0, y0, y1, fx, fy);

    int base = face * R * R + x0;
    uint4 e0 = __ldg(tex + base + y0 * R);
    uint4 e1 = __ldg(tex + base + y1 * R);

    float2 A0 = __half22float2(*reinterpret_cast<const __half2*>(&e0.x));
    float2 B0 = __half22float2(*reinterpret_cast<const __half2*>(&e0.y));
    float2 C0 = __half22float2(*reinterpret_cast<const __half2*>(&e0.z));
    float2 A1 = __half22float2(*reinterpret_cast<const __half2*>(&e1.x));
    float2 B1 = __half22float2(*reinterpret_cast<const __half2*>(&e1.y));
    float2 C1 = __half22float2(*reinterpret_cast<const __half2*>(&e1.z));

    float r0 = A0.x + fx * (B0.y - A0.x);
    float g0 = A0.y + fx * (C0.x - A0.y);
    float b0 = B0.x + fx * (C0.y - B0.x);
    float r1 = A1.x + fx * (B1.y - A1.x);
    float g1 = A1.y + fx * (C1.x - A1.y);
    float b1 = B1.x + fx * (C1.y - B1.x);

    float3x r;
    r.x = r0 + fy * (r1 - r0);
    r.y = g0 + fy * (g1 - g0);
    r.z = b0 + fy * (b1 - b0);
    return r;
}

__device__ __forceinline__ float linear2srgb(float x) {
    float l = __log2f(x);
    float y = l * (1.0f / 2.4f);
    float fl = floorf(y);
    float t = y - fl;
    float p = fmaf(t,
              fmaf(t,
              fmaf(t,
              fmaf(t,
              fmaf(t, 0.0013333558f, 0.0096181291f),
                       0.0555041087f),
                       0.2402265070f),
                       0.6931471806f),
                       1.0f);
    int e = (int)fl;
    float r = __int_as_float(__float_as_int(p) + (e << 23));
    float hi = fmaf(1.055f, r, -0.055f);
    return (x > 0.0031308f) ? hi : 12.92f * x;
}

__global__ void __launch_bounds__(256, 5)
envlight_kernel1(const float* __restrict__ gb_pos,
                 const float* __restrict__ gb_normal,
                 const float* __restrict__ basecolor,
                 const float* __restrict__ metallic,
                 const float* __restrict__ roughness,
                 const float* __restrict__ view_pos,
                 float* __restrict__ out,
                 int n) {
    int i = blockIdx.x * blockDim.x + threadIdx.x;
    if (i >= n) return;

    float vx = __ldg(view_pos + 0);
    float vy = __ldg(view_pos + 1);
    float vz = __ldg(view_pos + 2);

    float px = gb_pos[i * 3 + 0];
    float py = gb_pos[i * 3 + 1];
    float pz = gb_pos[i * 3 + 2];
    float nx = gb_normal[i * 3 + 0];
    float ny = gb_normal[i * 3 + 1];
    float nz = gb_normal[i * 3 + 2];
    float bcx = basecolor[i * 3 + 0];
    float bcy = basecolor[i * 3 + 1];
    float bcz = basecolor[i * 3 + 2];
    float met = metallic[i];
    float rough = roughness[i];

    // wo left unnormalized; only NdotV needs the normalization factor.
    float wx = vx - px, wy = vy - py, wz = vz - pz;
    float wlen2 = fmaxf(wx * wx + wy * wy + wz * wz, 1e-20f);
    float winv = rsqrtf(wlen2);

    float om = 1.0f - met;
    float dax = om * bcx, day = om * bcy, daz = om * bcz;
    float sax = 0.04f * om + met * bcx;
    float say = 0.04f * om + met * bcy;
    float saz = 0.04f * om + met * bcz;

    float d_un = wx * nx + wy * ny + wz * nz;
    float rx = 2.0f * d_un * nx - wx;
    float ry = 2.0f * d_un * ny - wy;
    float rz = 2.0f * d_un * nz - wz;

    // ambient from diffuse cubemap (16^2, fp16 pairs)
    int dface; float du, dv;
    cube_face_uv(nx, ny, nz, dface, du, dv);
    float3x ambient = cube_bilinear_pair(g_diff, 16, dface, du, dv);

    float dlx = ambient.x * dax;
    float dly = ambient.y * day;
    float dlz = ambient.z * daz;

    // FG LUT (256x256x2, clamp, fp32 pairs)
    float NdotV = fmaxf(d_un * winv, 0.0001f);
    float fg0, fg1;
    {
        float tu = NdotV * 256.0f - 0.5f;
        float tv = rough * 256.0f - 0.5f;
        int x0, y0, y1; float fx, fy;
        pair_setup(256.0f, tu, tv, x0, y0, y1, fx, fy);
        float4 e0 = __ldg(g_fg + y0 * 256 + x0);
        float4 e1 = __ldg(g_fg + y1 * 256 + x0);
        float a0 = e0.x + fx * (e0.z - e0.x);
        float b0 = e0.y + fx * (e0.w - e0.y);
        float a1 = e1.x + fx * (e1.z - e1.x);
        float b1 = e1.y + fx * (e1.w - e1.y);
        fg0 = a0 + fy * (a1 - a0);
        fg1 = b0 + fy * (b1 - b0);
    }

    // mip
    float mip;
    {
        const float L = (float)N_MIPS;
        float lo = (fminf(fmaxf(rough, MIN_ROUGHNESS), MAX_ROUGHNESS) - MIN_ROUGHNESS)
                   * ((L - 2.0f) / (MAX_ROUGHNESS - MIN_ROUGHNESS));
        float hi = (fminf(fmaxf(rough, MAX_ROUGHNESS), 1.0f) - MAX_ROUGHNESS)
                   * (1.0f / (1.0f - MAX_ROUGHNESS)) + (L - 2.0f);
        mip = (rough < MAX_ROUGHNESS) ? lo : hi;
        mip = fminf(fmaxf(mip, 0.0f), L - 1.0f);
    }

    int sface; float su, sv;
    cube_face_uv(rx, ry, rz, sface, su, sv);

    int l0 = (int)floorf(mip);
    if (l0 > N_MIPS - 1) l0 = N_MIPS - 1;
    float f = mip - (float)l0;
    int l1 = l0 + 1;
    if (l1 > N_MIPS - 1) l1 = N_MIPS - 1;

    const uint4* t0 = g_spec + SPEC_OFF[l0];
    const uint4* t1 = g_spec + SPEC_OFF[l1];
    int R0 = 512 >> l0;
    int R1 = 512 >> l1;

    float3x s0 = cube_bilinear_pair(t0, R0, sface, su, sv);
    float3x s1 = cube_bilinear_pair(t1, R1, sface, su, sv);

    float spx = s0.x + f * (s1.x - s0.x);
    float spy = s0.y + f * (s1.y - s0.y);
    float spz = s0.z + f * (s1.z - s0.z);

    float refx = sax * fg0 + fg1;
    float refy = say * fg0 + fg1;
    float refz = saz * fg0 + fg1;

    float cx = fminf(fmaxf(spx * refx + dlx, 0.0f), 1.0f);
    float cy = fminf(fmaxf(spy * refy + dly, 0.0f), 1.0f);
    float cz = fminf(fmaxf(spz * refz + dlz, 0.0f), 1.0f);

    out[i * 3 + 0] = linear2srgb(cx);
    out[i * 3 + 1] = linear2srgb(cy);
    out[i * 3 + 2] = linear2srgb(cz);
}

extern "C" void kernel_launch(void* const* d_in, const int* in_sizes, int n_in,
                              void* d_out, int out_size) {
    const float* gb_pos    = (const float*)d_in[0];
    const float* gb_normal = (const float*)d_in[1];
    const float* basecolor = (const float*)d_in[2];
    const float* metallic  = (const float*)d_in[3];
    const float* roughness = (const float*)d_in[4];
    const float* view_pos  = (const float*)d_in[5];
    const float* diffuse   = (const float*)d_in[6];
    const float* fg_lut    = (const float*)d_in[7];

    SpecTable specs;
    specs.p[0] = (const float*)d_in[8];
    specs.p[1] = (const float*)d_in[9];
    specs.p[2] = (const float*)d_in[10];
    specs.p[3] = (const float*)d_in[11];
    specs.p[4] = (const float*)d_in[12];
    specs.p[5] = (const float*)d_in[13];

    float* out = (float*)d_out;
    int n = in_sizes[0] / 3;

    // Pass 1: repack all textures into paired-texel records
    {
        int chunks = SPEC_TOTAL_TEXELS / 4 + DIFF_TEXELS / 4 + FG_TEXELS / 4;
        int threads = 256;
        int blocks = (chunks + threads - 1) / threads;
        repack_kernel<<<blocks, threads>>>(specs, diffuse, fg_lut);
    }

    // Pass 2: shade, 1 px/thread at high occupancy
    {
        int threads = 256;
        int blocks = (n + threads - 1) / threads;
        envlight_kernel1<<<blocks, threads>>>(gb_pos, gb_normal, basecolor, metallic,
                                              roughness, view_pos, out, n);
    }
}

// round 8
// speedup vs baseline: 1.8327x; 1.2608x over previous
#include <cuda_runtime.h>
#include <cuda_fp16.h>
#include <math.h>

#define MIN_ROUGHNESS 0.08f
#define MAX_ROUGHNESS 0.5f
#define N_MIPS 6

// Paired array holds mips 1..5 only (mip0 sampled raw from the input buffer).
// Mip texel counts: m1=393216 m2=98304 m3=24576 m4=6144 m5=1536 -> 523776
#define PAIR_TOTAL_TEXELS 523776
#define DIFF_TEXELS 1536
#define FG_TEXELS 65536

__constant__ int PAIR_OFF[6] = {0, 393216, 491520, 516096, 522240, 523776};

// Paired-texel records: entry x holds texels x and x+1 (x+1 clamped at row end).
__device__ uint4  g_spec[PAIR_TOTAL_TEXELS];  // fp16 rgb|rgb (8.4 MB)
__device__ uint4  g_diff[DIFF_TEXELS];        // fp16 rgb|rgb (24 KB)
__device__ float4 g_fg[FG_TEXELS];            // fp32 (fg0,fg1)|(fg0,fg1) (1 MB)

struct SpecTable {
    const float* p[N_MIPS];
};

struct float3x { float x, y, z; };

// ---------------------------------------------------------------------------
// Repack pass (mips 1..5 + diffuse + fg only; ~16 MB traffic)
// ---------------------------------------------------------------------------
__device__ __forceinline__ uint4 pack_pair(float lr, float lg, float lb,
                                           float hr, float hg, float hb) {
    __half2 A = __floats2half2_rn(lr, lg);
    __half2 B = __floats2half2_rn(lb, hr);
    __half2 C = __floats2half2_rn(hg, hb);
    uint4 o;
    o.x = *reinterpret_cast<unsigned int*>(&A);
    o.y = *reinterpret_cast<unsigned int*>(&B);
    o.z = *reinterpret_cast<unsigned int*>(&C);
    o.w = 0u;
    return o;
}

__device__ __forceinline__ void repack_rgb_chunk(const float* __restrict__ in,
                                                 uint4* __restrict__ out,
                                                 int local, int R) {
    int x = local % R;
    const float4* p = (const float4*)(in + (size_t)local * 3);
    float4 a = __ldg(p + 0);
    float4 b = __ldg(p + 1);
    float4 c = __ldg(p + 2);
    float f[16];
    f[0] = a.x; f[1] = a.y; f[2]  = a.z; f[3]  = a.w;
    f[4] = b.x; f[5] = b.y; f[6]  = b.z; f[7]  = b.w;
    f[8] = c.x; f[9] = c.y; f[10] = c.z; f[11] = c.w;
    bool has_next = (x + 4 < R);
    if (has_next) {
        float4 d = __ldg(p + 3);
        f[12] = d.x; f[13] = d.y; f[14] = d.z; f[15] = d.w;
    } else {
        f[12] = f[9]; f[13] = f[10]; f[14] = f[11]; f[15] = 0.0f;
    }
    #pragma unroll
    for (int i = 0; i < 4; i++) {
        out[local + i] = pack_pair(f[3 * i + 0], f[3 * i + 1], f[3 * i + 2],
                                   f[3 * i + 3], f[3 * i + 4], f[3 * i + 5]);
    }
}

__global__ void __launch_bounds__(256)
repack_kernel(SpecTable specs, const float* __restrict__ diffuse,
              const float* __restrict__ fg_lut) {
    const int QS = PAIR_TOTAL_TEXELS / 4;   // 130944
    const int QD = QS + DIFF_TEXELS / 4;    // +384
    const int QF = QD + FG_TEXELS / 4;      // +16384
    int q = blockIdx.x * blockDim.x + threadIdx.x;
    if (q >= QF) return;

    if (q < QS) {
        int t = q * 4;
        int lvl = 1;
        if (t >= 393216) lvl = 2;
        if (t >= 491520) lvl = 3;
        if (t >= 516096) lvl = 4;
        if (t >= 522240) lvl = 5;
        int local = t - PAIR_OFF[lvl - 1];
        repack_rgb_chunk(specs.p[lvl], g_spec + PAIR_OFF[lvl - 1], local, 512 >> lvl);
    } else if (q < QD) {
        int local = (q - QS) * 4;
        repack_rgb_chunk(diffuse, g_diff, local, 16);
    } else {
        int t = (q - QD) * 4;
        int x = t % 256;
        const float4* p = (const float4*)(fg_lut + (size_t)t * 2);
        float4 a = __ldg(p + 0);
        float4 b = __ldg(p + 1);
        float f[12];
        f[0] = a.x; f[1] = a.y; f[2] = a.z; f[3] = a.w;
        f[4] = b.x; f[5] = b.y; f[6] = b.z; f[7] = b.w;
        bool has_next = (x + 4 < 256);
        if (has_next) {
            float4 c = __ldg(p + 2);
            f[8] = c.x; f[9] = c.y; f[10] = c.z; f[11] = c.w;
        } else {
            f[8] = f[6]; f[9] = f[7]; f[10] = 0.0f; f[11] = 0.0f;
        }
        #pragma unroll
        for (int i = 0; i < 4; i++) {
            g_fg[t + i] = make_float4(f[2 * i + 0], f[2 * i + 1],
                                      f[2 * i + 2], f[2 * i + 3]);
        }
    }
}

// ---------------------------------------------------------------------------
// Main shading kernel
// ---------------------------------------------------------------------------
__device__ __forceinline__ void cube_face_uv(float x, float y, float z,
                                             int& face, float& u, float& v) {
    float ax = fabsf(x), ay = fabsf(y), az = fabsf(z);
    bool is_x = (ax >= ay) && (ax >= az);
    bool is_y = (!is_x) && (ay >= az);
    face = is_x ? (x >= 0.0f ? 0 : 1)
                : (is_y ? (y >= 0.0f ? 2 : 3)
                        : (z >= 0.0f ? 4 : 5));
    float ma = fmaxf(is_x ? ax : (is_y ? ay : az), 1e-20f);
    float un = (face == 0) ? -z : (face == 1) ? z : (face == 5) ? -x : x;
    float vn = (face == 2) ? z : (face == 3) ? -z : -y;
    float inv = __fdividef(1.0f, ma);
    u = un * inv;
    v = vn * inv;
}

__device__ __forceinline__ void pair_setup(float Rf, float tu, float tv,
                                           int& x0, int& y0, int& y1,
                                           float& fx, float& fy) {
    float x0f = floorf(tu);
    float y0f = floorf(tv);
    fx = tu - x0f;
    if (x0f < 0.0f) fx = 0.0f;
    fy = tv - y0f;
    x0 = (int)fminf(fmaxf(x0f, 0.0f), Rf - 1.0f);
    y0 = (int)fminf(fmaxf(y0f, 0.0f), Rf - 1.0f);
    y1 = (int)fminf(fmaxf(y0f + 1.0f, 0.0f), Rf - 1.0f);
}

__device__ __forceinline__ float3x cube_bilinear_pair(const uint4* __restrict__ tex,
                                                      int R, int face,
                                                      float u, float v) {
    float Rf = (float)R;
    float tu = fmaf(u, 0.5f * Rf, 0.5f * Rf - 0.5f);
    float tv = fmaf(v, 0.5f * Rf, 0.5f * Rf - 0.5f);
    int x0, y0, y1; float fx, fy;
    pair_setup(Rf, tu, tv, x0, y0, y1, fx, fy);

    int base = face * R * R + x0;
    uint4 e0 = __ldg(tex + base + y0 * R);
    uint4 e1 = __ldg(tex + base + y1 * R);

    float2 A0 = __half22float2(*reinterpret_cast<const __half2*>(&e0.x));
    float2 B0 = __half22float2(*reinterpret_cast<const __half2*>(&e0.y));
    float2 C0 = __half22float2(*reinterpret_cast<const __half2*>(&e0.z));
    float2 A1 = __half22float2(*reinterpret_cast<const __half2*>(&e1.x));
    float2 B1 = __half22float2(*reinterpret_cast<const __half2*>(&e1.y));
    float2 C1 = __half22float2(*reinterpret_cast<const __half2*>(&e1.z));

    float r0 = A0.x + fx * (B0.y - A0.x);
    float g0 = A0.y + fx * (C0.x - A0.y);
    float b0 = B0.x + fx * (C0.y - B0.x);
    float r1 = A1.x + fx * (B1.y - A1.x);
    float g1 = A1.y + fx * (C1.x - A1.y);
    float b1 = B1.x + fx * (C1.y - B1.x);

    float3x r;
    r.x = r0 + fy * (r1 - r0);
    r.y = g0 + fy * (g1 - g0);
    r.z = b0 + fy * (b1 - b0);
    return r;
}

// Raw fp32 RGB bilinear on the original mip-0 buffer (exact).
__device__ __forceinline__ float3x cube_bilinear_raw(const float* __restrict__ tex,
                                                     int face, float u, float v) {
    const float Rf = 512.0f;
    float tu = fmaf(u, 0.5f * Rf, 0.5f * Rf - 0.5f);
    float tv = fmaf(v, 0.5f * Rf, 0.5f * Rf - 0.5f);
    float x0f = floorf(tu);
    float y0f = floorf(tv);
    float fx = tu - x0f;
    float fy = tv - y0f;
    int x0 = (int)fminf(fmaxf(x0f, 0.0f), Rf - 1.0f);
    int x1 = (int)fminf(fmaxf(x0f + 1.0f, 0.0f), Rf - 1.0f);
    int y0 = (int)fminf(fmaxf(y0f, 0.0f), Rf - 1.0f);
    int y1 = (int)fminf(fmaxf(y0f + 1.0f, 0.0f), Rf - 1.0f);

    int baseF = face * 512 * 512;
    int i00 = (baseF + y0 * 512 + x0) * 3;
    int i01 = (baseF + y0 * 512 + x1) * 3;
    int i10 = (baseF + y1 * 512 + x0) * 3;
    int i11 = (baseF + y1 * 512 + x1) * 3;

    float w00 = (1.0f - fx) * (1.0f - fy);
    float w01 = fx * (1.0f - fy);
    float w10 = (1.0f - fx) * fy;
    float w11 = fx * fy;

    float3x r;
    r.x = __ldg(tex + i00 + 0) * w00 + __ldg(tex + i01 + 0) * w01 +
          __ldg(tex + i10 + 0) * w10 + __ldg(tex + i11 + 0) * w11;
    r.y = __ldg(tex + i00 + 1) * w00 + __ldg(tex + i01 + 1) * w01 +
          __ldg(tex + i10 + 1) * w10 + __ldg(tex + i11 + 1) * w11;
    r.z = __ldg(tex + i00 + 2) * w00 + __ldg(tex + i01 + 2) * w01 +
          __ldg(tex + i10 + 2) * w10 + __ldg(tex + i11 + 2) * w11;
    return r;
}

__device__ __forceinline__ float linear2srgb(float x) {
    float l = __log2f(x);
    float y = l * (1.0f / 2.4f);
    float fl = floorf(y);
    float t = y - fl;
    float p = fmaf(t,
              fmaf(t,
              fmaf(t,
              fmaf(t,
              fmaf(t, 0.0013333558f, 0.0096181291f),
                       0.0555041087f),
                       0.2402265070f),
                       0.6931471806f),
                       1.0f);
    int e = (int)fl;
    float r = __int_as_float(__float_as_int(p) + (e << 23));
    float hi = fmaf(1.055f, r, -0.055f);
    return (x > 0.0031308f) ? hi : 12.92f * x;
}

__global__ void __launch_bounds__(256, 5)
envlight_kernel1(const float* __restrict__ gb_pos,
                 const float* __restrict__ gb_normal,
                 const float* __restrict__ basecolor,
                 const float* __restrict__ metallic,
                 const float* __restrict__ roughness,
                 const float* __restrict__ view_pos,
                 const float* __restrict__ spec0,
                 float* __restrict__ out,
                 int n) {
    int i = blockIdx.x * blockDim.x + threadIdx.x;
    if (i >= n) return;

    float vx = __ldg(view_pos + 0);
    float vy = __ldg(view_pos + 1);
    float vz = __ldg(view_pos + 2);

    float px = gb_pos[i * 3 + 0];
    float py = gb_pos[i * 3 + 1];
    float pz = gb_pos[i * 3 + 2];
    float nx = gb_normal[i * 3 + 0];
    float ny = gb_normal[i * 3 + 1];
    float nz = gb_normal[i * 3 + 2];
    float bcx = basecolor[i * 3 + 0];
    float bcy = basecolor[i * 3 + 1];
    float bcz = basecolor[i * 3 + 2];
    float met = metallic[i];
    float rough = roughness[i];

    // wo left unnormalized; only NdotV needs the normalization factor.
    float wx = vx - px, wy = vy - py, wz = vz - pz;
    float wlen2 = fmaxf(wx * wx + wy * wy + wz * wz, 1e-20f);
    float winv = rsqrtf(wlen2);

    float om = 1.0f - met;
    float dax = om * bcx, day = om * bcy, daz = om * bcz;
    float sax = 0.04f * om + met * bcx;
    float say = 0.04f * om + met * bcy;
    float saz = 0.04f * om + met * bcz;

    float d_un = wx * nx + wy * ny + wz * nz;
    float rx = 2.0f * d_un * nx - wx;
    float ry = 2.0f * d_un * ny - wy;
    float rz = 2.0f * d_un * nz - wz;

    // ambient from diffuse cubemap (16^2, fp16 pairs)
    int dface; float du, dv;
    cube_face_uv(nx, ny, nz, dface, du, dv);
    float3x ambient = cube_bilinear_pair(g_diff, 16, dface, du, dv);

    float dlx = ambient.x * dax;
    float dly = ambient.y * day;
    float dlz = ambient.z * daz;

    // FG LUT (256x256x2, clamp, fp32 pairs)
    float NdotV = fmaxf(d_un * winv, 0.0001f);
    float fg0, fg1;
    {
        float tu = NdotV * 256.0f - 0.5f;
        float tv = rough * 256.0f - 0.5f;
        int x0, y0, y1; float fx, fy;
        pair_setup(256.0f, tu, tv, x0, y0, y1, fx, fy);
        float4 e0 = __ldg(g_fg + y0 * 256 + x0);
        float4 e1 = __ldg(g_fg + y1 * 256 + x0);
        float a0 = e0.x + fx * (e0.z - e0.x);
        float b0 = e0.y + fx * (e0.w - e0.y);
        float a1 = e1.x + fx * (e1.z - e1.x);
        float b1 = e1.y + fx * (e1.w - e1.y);
        fg0 = a0 + fy * (a1 - a0);
        fg1 = b0 + fy * (b1 - b0);
    }

    // mip
    float mip;
    {
        const float L = (float)N_MIPS;
        float lo = (fminf(fmaxf(rough, MIN_ROUGHNESS), MAX_ROUGHNESS) - MIN_ROUGHNESS)
                   * ((L - 2.0f) / (MAX_ROUGHNESS - MIN_ROUGHNESS));
        float hi = (fminf(fmaxf(rough, MAX_ROUGHNESS), 1.0f) - MAX_ROUGHNESS)
                   * (1.0f / (1.0f - MAX_ROUGHNESS)) + (L - 2.0f);
        mip = (rough < MAX_ROUGHNESS) ? lo : hi;
        mip = fminf(fmaxf(mip, 0.0f), L - 1.0f);
    }

    int sface; float su, sv;
    cube_face_uv(rx, ry, rz, sface, su, sv);

    int l0 = (int)floorf(mip);
    if (l0 > N_MIPS - 1) l0 = N_MIPS - 1;
    float f = mip - (float)l0;
    int l1 = l0 + 1;
    if (l1 > N_MIPS - 1) l1 = N_MIPS - 1;   // f==0 there

    // s1 always lives in the paired array (l1 >= 1 always).
    float3x s1 = cube_bilinear_pair(g_spec + PAIR_OFF[l1 - 1], 512 >> l1,
                                    sface, su, sv);
    // s0: raw fp32 mip0 if l0==0 (~18.5% of pixels), else paired.
    float3x s0;
    if (l0 == 0) {
        s0 = cube_bilinear_raw(spec0, sface, su, sv);
    } else {
        s0 = cube_bilinear_pair(g_spec + PAIR_OFF[l0 - 1], 512 >> l0,
                                sface, su, sv);
    }

    float spx = s0.x + f * (s1.x - s0.x);
    float spy = s0.y + f * (s1.y - s0.y);
    float spz = s0.z + f * (s1.z - s0.z);

    float refx = sax * fg0 + fg1;
    float refy = say * fg0 + fg1;
    float refz = saz * fg0 + fg1;

    float cx = fminf(fmaxf(spx * refx + dlx, 0.0f), 1.0f);
    float cy = fminf(fmaxf(spy * refy + dly, 0.0f), 1.0f);
    float cz = fminf(fmaxf(spz * refz + dlz, 0.0f), 1.0f);

    out[i * 3 + 0] = linear2srgb(cx);
    out[i * 3 + 1] = linear2srgb(cy);
    out[i * 3 + 2] = linear2srgb(cz);
}

extern "C" void kernel_launch(void* const* d_in, const int* in_sizes, int n_in,
                              void* d_out, int out_size) {
    const float* gb_pos    = (const float*)d_in[0];
    const float* gb_normal = (const float*)d_in[1];
    const float* basecolor = (const float*)d_in[2];
    const float* metallic  = (const float*)d_in[3];
    const float* roughness = (const float*)d_in[4];
    const float* view_pos  = (const float*)d_in[5];
    const float* diffuse   = (const float*)d_in[6];
    const float* fg_lut    = (const float*)d_in[7];

    SpecTable specs;
    specs.p[0] = (const float*)d_in[8];
    specs.p[1] = (const float*)d_in[9];
    specs.p[2] = (const float*)d_in[10];
    specs.p[3] = (const float*)d_in[11];
    specs.p[4] = (const float*)d_in[12];
    specs.p[5] = (const float*)d_in[13];

    float* out = (float*)d_out;
    int n = in_sizes[0] / 3;

    // Pass 1: repack mips 1..5 + diffuse + fg (small; mip0 stays raw)
    {
        int chunks = PAIR_TOTAL_TEXELS / 4 + DIFF_TEXELS / 4 + FG_TEXELS / 4;
        int threads = 256;
        int blocks = (chunks + threads - 1) / threads;
        repack_kernel<<<blocks, threads>>>(specs, diffuse, fg_lut);
    }

    // Pass 2: shade, 1 px/thread
    {
        int threads = 256;
        int blocks = (n + threads - 1) / threads;
        envlight_kernel1<<<blocks, threads>>>(gb_pos, gb_normal, basecolor, metallic,
                                              roughness, view_pos, specs.p[0], out, n);
    }
}